// round 1
// baseline (speedup 1.0000x reference)
#include <cuda_runtime.h>
#include <math.h>

#define BB   64
#define SS   512
#define EE   128
#define HH   128
#define GG   512          // 4*H
#define FWW  6
#define WW   507          // S - FW + 1
#define NTOK (BB*SS)      // 32768
#define MT   64           // windows/tokens per CTA
#define NTHREADS 256

// Scratch (device globals: allocation is forbidden)
__device__ float g_xproj[(size_t)NTOK * GG];   // 64 MB: per-token input projection (+bias)
__device__ float g_hout[(size_t)BB * WW * HH]; // 16.6 MB: final h per window

__device__ __forceinline__ float sigmoidf_(float x) { return 1.0f / (1.0f + expf(-x)); }

// ---------------------------------------------------------------------------
// Kernel 1: xproj[tok][g] = embed[inputs[tok]] . w_ih[g] + b_ih[g] + b_hh[g]
// GEMM tile: 64 tokens x 512 gates, K=128. smem: w chunk [k][n] 64KB + emb [k][m] 32KB.
// ---------------------------------------------------------------------------
__global__ __launch_bounds__(NTHREADS, 1)
void xproj_kernel(const int* __restrict__ inputs,
                  const float* __restrict__ embed,
                  const float* __restrict__ w_ih,
                  const float* __restrict__ b_ih,
                  const float* __restrict__ b_hh)
{
    extern __shared__ float smem[];
    float* w_s   = smem;             // [128][128], w_s[k][n]
    float* emb_s = smem + 128 * 128; // [128][64],  emb_s[k][m]

    const int tid = threadIdx.x;
    const int t0  = blockIdx.x * MT;

    // Gather embeddings, store transposed (lanes -> consecutive tokens: conflict-free STS)
    {
        const int tl  = tid & 63;
        const int th  = tid >> 6;                  // 0..3
        const int row = inputs[t0 + tl];
        const float* erow = embed + (size_t)row * EE;
        #pragma unroll
        for (int i = 0; i < 8; ++i) {
            int e0 = (4 * i + th) * 4;             // covers 0..124 step 4
            float4 v = *(const float4*)&erow[e0];
            emb_s[(e0 + 0) * MT + tl] = v.x;
            emb_s[(e0 + 1) * MT + tl] = v.y;
            emb_s[(e0 + 2) * MT + tl] = v.z;
            emb_s[(e0 + 3) * MT + tl] = v.w;
        }
    }

    const int m0 = (tid & 7) * 8;    // 8 tokens per thread
    const int j0 = (tid >> 3) * 4;   // 4 gates per thread (within 128-chunk)

    for (int gs = 0; gs < 4; ++gs) {
        __syncthreads();
        // Load w_ih chunk transposed: w_s[k][n] = w_ih[gs*128+n][k]
        {
            const int gl = tid & 127;
            const int gh = tid >> 7;               // 0..1
            const float* wrow = w_ih + (size_t)(gs * 128 + gl) * EE;
            #pragma unroll
            for (int i = 0; i < 16; ++i) {
                int k0 = (2 * i + gh) * 4;         // covers 0..124 step 4
                float4 v = *(const float4*)&wrow[k0];
                w_s[(k0 + 0) * 128 + gl] = v.x;
                w_s[(k0 + 1) * 128 + gl] = v.y;
                w_s[(k0 + 2) * 128 + gl] = v.z;
                w_s[(k0 + 3) * 128 + gl] = v.w;
            }
        }
        __syncthreads();

        float acc[8][4];
        {
            float bias[4];
            #pragma unroll
            for (int ij = 0; ij < 4; ++ij)
                bias[ij] = b_ih[gs * 128 + j0 + ij] + b_hh[gs * 128 + j0 + ij];
            #pragma unroll
            for (int im = 0; im < 8; ++im)
                #pragma unroll
                for (int ij = 0; ij < 4; ++ij) acc[im][ij] = bias[ij];
        }

        #pragma unroll 4
        for (int k = 0; k < EE; ++k) {
            float4 b4 = *(float4*)&w_s[k * 128 + j0];
            float4 a0 = *(float4*)&emb_s[k * MT + m0];
            float4 a1 = *(float4*)&emb_s[k * MT + m0 + 4];
            float a[8] = {a0.x, a0.y, a0.z, a0.w, a1.x, a1.y, a1.z, a1.w};
            float bv[4] = {b4.x, b4.y, b4.z, b4.w};
            #pragma unroll
            for (int im = 0; im < 8; ++im)
                #pragma unroll
                for (int ij = 0; ij < 4; ++ij)
                    acc[im][ij] = fmaf(a[im], bv[ij], acc[im][ij]);
        }

        #pragma unroll
        for (int im = 0; im < 8; ++im) {
            float4 o = make_float4(acc[im][0], acc[im][1], acc[im][2], acc[im][3]);
            *(float4*)&g_xproj[(size_t)(t0 + m0 + im) * GG + gs * 128 + j0] = o;
        }
    }
}

// ---------------------------------------------------------------------------
// Kernel 2: 6-step LSTM over 64 windows per CTA.
//   t=0: gates = xproj (h=0, no GEMM). t>=1: gates = xproj + h @ w_hh.T.
// h lives in smem K-major [j][m]; c and gate accumulators in registers.
// ---------------------------------------------------------------------------
__global__ __launch_bounds__(NTHREADS, 1)
void lstm_kernel(const float* __restrict__ w_hh)
{
    extern __shared__ float smem[];
    float* w_s = smem;             // [128][128]
    float* h_s = smem + 128 * 128; // [128][64], h_s[j][m]

    const int tid = threadIdx.x;
    const int b   = blockIdx.y;
    const int w0  = blockIdx.x * MT;

    const int m0 = (tid & 7) * 8;
    const int j0 = (tid >> 3) * 4;

    float c[8][4];
    float h[8][4];
    #pragma unroll
    for (int im = 0; im < 8; ++im)
        #pragma unroll
        for (int ij = 0; ij < 4; ++ij) c[im][ij] = 0.0f;

    int wv[8];
    #pragma unroll
    for (int im = 0; im < 8; ++im) {
        int w_ = w0 + m0 + im;
        wv[im] = (w_ < WW) ? w_ : (WW - 1);   // clamp reads; invalid windows never stored
    }
    const size_t tokbase = (size_t)b * SS;

    const int gl = tid & 127;
    const int gh = tid >> 7;

    for (int t = 0; t < FWW; ++t) {
        float acc[4][8][4];
        // init accumulators from xproj (includes bias)
        #pragma unroll
        for (int gs = 0; gs < 4; ++gs)
            #pragma unroll
            for (int im = 0; im < 8; ++im) {
                float4 x4 = *(const float4*)&g_xproj[(tokbase + wv[im] + t) * GG + gs * 128 + j0];
                acc[gs][im][0] = x4.x; acc[gs][im][1] = x4.y;
                acc[gs][im][2] = x4.z; acc[gs][im][3] = x4.w;
            }

        if (t > 0) {
            for (int gs = 0; gs < 4; ++gs) {
                __syncthreads();   // protect w_s (and, at gs=0, h_s writes from prev step)
                {
                    const float* wrow = w_hh + (size_t)(gs * 128 + gl) * HH;
                    #pragma unroll
                    for (int i = 0; i < 16; ++i) {
                        int k0 = (2 * i + gh) * 4;
                        float4 v = *(const float4*)&wrow[k0];
                        w_s[(k0 + 0) * 128 + gl] = v.x;
                        w_s[(k0 + 1) * 128 + gl] = v.y;
                        w_s[(k0 + 2) * 128 + gl] = v.z;
                        w_s[(k0 + 3) * 128 + gl] = v.w;
                    }
                }
                __syncthreads();

                #pragma unroll 4
                for (int k = 0; k < HH; ++k) {
                    float4 b4 = *(float4*)&w_s[k * 128 + j0];
                    float4 a0 = *(float4*)&h_s[k * MT + m0];
                    float4 a1 = *(float4*)&h_s[k * MT + m0 + 4];
                    float a[8] = {a0.x, a0.y, a0.z, a0.w, a1.x, a1.y, a1.z, a1.w};
                    float bv[4] = {b4.x, b4.y, b4.z, b4.w};
                    #pragma unroll
                    for (int im = 0; im < 8; ++im)
                        #pragma unroll
                        for (int ij = 0; ij < 4; ++ij)
                            acc[gs][im][ij] = fmaf(a[im], bv[ij], acc[gs][im][ij]);
                }
            }
        }

        __syncthreads();  // all GEMM reads of h_s done before rewrite

        // LSTM cell (register-local: same (m, j) ownership across all 4 gate chunks)
        #pragma unroll
        for (int im = 0; im < 8; ++im)
            #pragma unroll
            for (int ij = 0; ij < 4; ++ij) {
                float gi = acc[0][im][ij];
                float gf = acc[1][im][ij];
                float gg = acc[2][im][ij];
                float go = acc[3][im][ij];
                float cn = sigmoidf_(gf) * c[im][ij] + sigmoidf_(gi) * tanhf(gg);
                c[im][ij] = cn;
                h[im][ij] = sigmoidf_(go) * tanhf(cn);
            }

        if (t < FWW - 1) {
            // write h transposed into h_s for next step's GEMM
            #pragma unroll
            for (int ij = 0; ij < 4; ++ij) {
                float4 v0 = make_float4(h[0][ij], h[1][ij], h[2][ij], h[3][ij]);
                float4 v1 = make_float4(h[4][ij], h[5][ij], h[6][ij], h[7][ij]);
                *(float4*)&h_s[(j0 + ij) * MT + m0]     = v0;
                *(float4*)&h_s[(j0 + ij) * MT + m0 + 4] = v1;
            }
        }
    }

    // store final h for valid windows
    #pragma unroll
    for (int im = 0; im < 8; ++im) {
        int w_ = w0 + m0 + im;
        if (w_ < WW) {
            float4 o = make_float4(h[im][0], h[im][1], h[im][2], h[im][3]);
            *(float4*)&g_hout[((size_t)b * WW + w_) * HH + j0] = o;
        }
    }
}

// ---------------------------------------------------------------------------
// Kernel 3: feat[b][j] = max_w h_last[b][w][j];  out[b][c] = feat . fc_w[c] + fc_b[c]
// ---------------------------------------------------------------------------
__global__ void pool_fc_kernel(const float* __restrict__ fc_w,
                               const float* __restrict__ fc_b,
                               float* __restrict__ out)
{
    __shared__ float feat[HH];
    const int b = blockIdx.x;
    const int j = threadIdx.x;   // 128 threads

    float m = -1e30f;
    const float* base = g_hout + (size_t)b * WW * HH + j;
    for (int w = 0; w < WW; ++w) m = fmaxf(m, base[(size_t)w * HH]);
    feat[j] = m;
    __syncthreads();

    if (j < 2) {
        float s = fc_b[j];
        #pragma unroll 8
        for (int k = 0; k < HH; ++k) s += feat[k] * fc_w[j * HH + k];
        out[b * 2 + j] = s;
    }
}

// ---------------------------------------------------------------------------
extern "C" void kernel_launch(void* const* d_in, const int* in_sizes, int n_in,
                              void* d_out, int out_size)
{
    const int*   inputs = (const int*)  d_in[0];
    // d_in[1] = lengths : unused by the reference
    const float* embed  = (const float*)d_in[2];
    const float* w_ih   = (const float*)d_in[3];
    const float* w_hh   = (const float*)d_in[4];
    const float* b_ih   = (const float*)d_in[5];
    const float* b_hh   = (const float*)d_in[6];
    const float* fc_w   = (const float*)d_in[7];
    const float* fc_b   = (const float*)d_in[8];
    float* out = (float*)d_out;

    const size_t smem = (size_t)(128 * 128 + 128 * MT) * sizeof(float);  // 96 KB

    cudaFuncSetAttribute(xproj_kernel, cudaFuncAttributeMaxDynamicSharedMemorySize, (int)smem);
    cudaFuncSetAttribute(lstm_kernel,  cudaFuncAttributeMaxDynamicSharedMemorySize, (int)smem);

    xproj_kernel<<<NTOK / MT, NTHREADS, smem>>>(inputs, embed, w_ih, b_ih, b_hh);
    lstm_kernel<<<dim3((WW + MT - 1) / MT, BB), NTHREADS, smem>>>(w_hh);
    pool_fc_kernel<<<BB, HH>>>(fc_w, fc_b, out);
}

// round 2
// speedup vs baseline: 2.7651x; 2.7651x over previous
#include <cuda_runtime.h>
#include <math.h>

#define BB   64
#define SS   512
#define EE   128
#define HH   128
#define GG   512          // 4*H
#define FWW  6
#define WW   507          // S - FW + 1
#define NTOK (BB*SS)      // 32768
#define MT   64           // rows (tokens/windows) per CTA
#define NTHREADS 256

// Scratch (device globals: allocation is forbidden)
__device__ float g_xproj[(size_t)NTOK * GG];   // 64 MB: per-token input projection (+bias)
__device__ float g_hout[(size_t)BB * WW * HH]; // 16.6 MB: final h per window
__device__ float g_wih32[GG * EE];             // tf32-rounded w_ih
__device__ float g_whh32[GG * HH];             // tf32-rounded w_hh

// ---------------------------------------------------------------------------
// helpers
// ---------------------------------------------------------------------------
__device__ __forceinline__ float f2tf(float x) {
    unsigned u;
    asm("cvt.rna.tf32.f32 %0, %1;" : "=r"(u) : "f"(x));
    return __uint_as_float(u);
}
__device__ __forceinline__ float ex2f_(float x) { float y; asm("ex2.approx.f32 %0, %1;" : "=f"(y) : "f"(x)); return y; }
__device__ __forceinline__ float rcpf_(float x) { float y; asm("rcp.approx.f32 %0, %1;" : "=f"(y) : "f"(x)); return y; }
__device__ __forceinline__ float sigm_(float x) { return rcpf_(1.0f + ex2f_(-1.4426950408889634f * x)); }
__device__ __forceinline__ float tanh_(float x) {
    // tanh = 1 - 2/(e^{2x}+1); saturates correctly at +-inf of ex2
    float e = ex2f_(2.8853900817779268f * x);
    return fmaf(-2.0f, rcpf_(e + 1.0f), 1.0f);
}

__device__ __forceinline__ void mma_tf32(float* d, const unsigned* a, unsigned b0, unsigned b1) {
    asm("mma.sync.aligned.m16n8k8.row.col.f32.tf32.tf32.f32 "
        "{%0,%1,%2,%3},{%4,%5,%6,%7},{%8,%9},{%0,%1,%2,%3};"
        : "+f"(d[0]), "+f"(d[1]), "+f"(d[2]), "+f"(d[3])
        : "r"(a[0]), "r"(a[1]), "r"(a[2]), "r"(a[3]), "r"(b0), "r"(b1));
}

// ---------------------------------------------------------------------------
// Kernel 0: round weights to tf32 once
// ---------------------------------------------------------------------------
__global__ void prep_kernel(const float* __restrict__ w_ih, const float* __restrict__ w_hh) {
    int i0 = blockIdx.x * blockDim.x + threadIdx.x;
    for (int i = i0; i < GG * EE; i += gridDim.x * blockDim.x) {
        g_wih32[i] = f2tf(w_ih[i]);
        g_whh32[i] = f2tf(w_hh[i]);
    }
}

// ---------------------------------------------------------------------------
// Shared GEMM geometry (both big kernels):
//   CTA 256 thr = 8 warps, warp grid 2(m) x 4(n).
//   M = 64 rows/CTA, N = 512 (4 gate chunks of 128), K = 128.
//   A tile in smem [64][132] fp32 (tf32-rounded values).
//   B chunks staged in smem, swizzled: float4 j = k4 ^ (n&7) within row n.
//   acc[4 gs][2 mt][4 nt][4] = 128 fp32 regs/thread.
// ---------------------------------------------------------------------------
#define A_STRIDE 132
#define A_FLOATS (MT * A_STRIDE)          // 8448
#define WCHUNK   (128 * 128)              // floats per staged chunk
#define SMEM_FLOATS (A_FLOATS + 2 * WCHUNK)

// stage chunk (2*gp+ci) of a tf32 weight matrix into w_s[ci]
__device__ __forceinline__ void stage_chunk(const float* __restrict__ wsrc, float* w_s,
                                            int chunk, int tid) {
    int n  = tid >> 1;       // 0..127
    int hk = tid & 1;        // k half
    const float4* src = (const float4*)(wsrc + (chunk * 128 + n) * 128);
    float4* dst = (float4*)w_s;
    #pragma unroll
    for (int i = 0; i < 16; ++i) {
        int k4 = hk * 16 + i;
        dst[n * 32 + (k4 ^ (n & 7))] = src[k4];
    }
}

// one K=128 GEMM pass over 2 staged chunks: acc[2gp+ci] += A x Bchunk
__device__ __forceinline__ void gemm_2chunks(const unsigned* __restrict__ au,
                                             const float* __restrict__ w_s,
                                             float acc[4][2][4][4],
                                             int gp, int m0w, int n0w, int g, int tq) {
    for (int ks = 0; ks < 16; ++ks) {
        unsigned a[2][4];
        int k0 = ks * 8 + tq;
        #pragma unroll
        for (int mt = 0; mt < 2; ++mt) {
            int r = (m0w + mt * 16 + g) * A_STRIDE;
            a[mt][0] = au[r + k0];
            a[mt][1] = au[r + 8 * A_STRIDE + k0];
            a[mt][2] = au[r + k0 + 4];
            a[mt][3] = au[r + 8 * A_STRIDE + k0 + 4];
        }
        #pragma unroll
        for (int ci = 0; ci < 2; ++ci) {
            const unsigned* wb = (const unsigned*)(w_s + ci * WCHUNK);
            #pragma unroll
            for (int nt = 0; nt < 4; ++nt) {
                int n = n0w + nt * 8 + g;
                int s = n & 7;
                unsigned b0 = wb[n * 128 + ((2 * ks)     ^ s) * 4 + tq];
                unsigned b1 = wb[n * 128 + ((2 * ks + 1) ^ s) * 4 + tq];
                #pragma unroll
                for (int mt = 0; mt < 2; ++mt)
                    mma_tf32(acc[2 * gp + ci][mt][nt], a[mt], b0, b1);
            }
        }
    }
}

// ---------------------------------------------------------------------------
// Kernel 1: xproj[tok][g] = emb(tok) . w_ih[g]^T + b_ih[g] + b_hh[g]
// ---------------------------------------------------------------------------
__global__ __launch_bounds__(NTHREADS, 1)
void xproj_kernel(const int* __restrict__ inputs,
                  const float* __restrict__ embed,
                  const float* __restrict__ b_ih,
                  const float* __restrict__ b_hh)
{
    extern __shared__ float smem[];
    float* a_s = smem;                 // [64][132]
    float* w_s = smem + A_FLOATS;      // 2 chunks

    const int tid  = threadIdx.x;
    const int lane = tid & 31;
    const int wid  = tid >> 5;
    const int g    = lane >> 2;
    const int tq   = lane & 3;
    const int m0w  = (wid >> 2) * 32;  // 0,32
    const int n0w  = (wid & 3) * 32;   // 0..96 within chunk
    const int t0   = blockIdx.x * MT;

    // gather embeddings (tf32-rounded) into a_s
    {
        int tl = tid >> 2, qd = tid & 3;
        const float4* erow = (const float4*)(embed + (size_t)inputs[t0 + tl] * EE);
        #pragma unroll
        for (int i = 0; i < 8; ++i) {
            int k4 = qd * 8 + i;
            float4 v = erow[k4];
            v.x = f2tf(v.x); v.y = f2tf(v.y); v.z = f2tf(v.z); v.w = f2tf(v.w);
            *(float4*)&a_s[tl * A_STRIDE + k4 * 4] = v;
        }
    }

    // acc init = bias (broadcast over rows)
    float acc[4][2][4][4];
    #pragma unroll
    for (int gs = 0; gs < 4; ++gs)
        #pragma unroll
        for (int nt = 0; nt < 4; ++nt) {
            int col = gs * 128 + n0w + nt * 8 + 2 * tq;
            float2 bi = *(const float2*)&b_ih[col];
            float2 bh = *(const float2*)&b_hh[col];
            float bx = bi.x + bh.x, by = bi.y + bh.y;
            #pragma unroll
            for (int mt = 0; mt < 2; ++mt) {
                acc[gs][mt][nt][0] = bx; acc[gs][mt][nt][1] = by;
                acc[gs][mt][nt][2] = bx; acc[gs][mt][nt][3] = by;
            }
        }

    const unsigned* au = (const unsigned*)a_s;
    #pragma unroll
    for (int gp = 0; gp < 2; ++gp) {
        __syncthreads();
        stage_chunk(g_wih32, w_s,          2 * gp,     tid);
        stage_chunk(g_wih32, w_s + WCHUNK, 2 * gp + 1, tid);
        __syncthreads();
        gemm_2chunks(au, w_s, acc, gp, m0w, n0w, g, tq);
    }

    // store
    #pragma unroll
    for (int gs = 0; gs < 4; ++gs)
        #pragma unroll
        for (int mt = 0; mt < 2; ++mt)
            #pragma unroll
            for (int hh = 0; hh < 2; ++hh) {
                int r = m0w + mt * 16 + g + 8 * hh;
                float* orow = g_xproj + (size_t)(t0 + r) * GG;
                #pragma unroll
                for (int nt = 0; nt < 4; ++nt) {
                    float2 v = make_float2(acc[gs][mt][nt][2 * hh], acc[gs][mt][nt][2 * hh + 1]);
                    *(float2*)&orow[gs * 128 + n0w + nt * 8 + 2 * tq] = v;
                }
            }
}

// ---------------------------------------------------------------------------
// Kernel 2: 6-step LSTM, 64 windows/CTA, tf32 tensor-core recurrence
// ---------------------------------------------------------------------------
__global__ __launch_bounds__(NTHREADS, 1)
void lstm_kernel()
{
    extern __shared__ float smem[];
    float* h_s = smem;                 // [64][132]
    float* w_s = smem + A_FLOATS;

    const int tid  = threadIdx.x;
    const int lane = tid & 31;
    const int wid  = tid >> 5;
    const int g    = lane >> 2;
    const int tq   = lane & 3;
    const int m0w  = (wid >> 2) * 32;
    const int n0w  = (wid & 3) * 32;

    const int b  = blockIdx.y;
    const int w0 = blockIdx.x * MT;
    const int tokbase = b * SS;

    // window per owned row (clamped)
    int wv[2][2];
    #pragma unroll
    for (int mt = 0; mt < 2; ++mt)
        #pragma unroll
        for (int hh = 0; hh < 2; ++hh) {
            int w_ = w0 + m0w + mt * 16 + g + 8 * hh;
            wv[mt][hh] = (w_ < WW) ? w_ : (WW - 1);
        }

    float c_st[2][4][4];
    #pragma unroll
    for (int mt = 0; mt < 2; ++mt)
        #pragma unroll
        for (int nt = 0; nt < 4; ++nt)
            #pragma unroll
            for (int q = 0; q < 4; ++q) c_st[mt][nt][q] = 0.0f;

    float hv[2][4][4];
    const unsigned* au = (const unsigned*)h_s;

    for (int t = 0; t < FWW; ++t) {
        float acc[4][2][4][4];
        // init from xproj (bias included)
        #pragma unroll
        for (int mt = 0; mt < 2; ++mt)
            #pragma unroll
            for (int hh = 0; hh < 2; ++hh) {
                const float* xr = g_xproj + (size_t)(tokbase + wv[mt][hh] + t) * GG;
                #pragma unroll
                for (int gs = 0; gs < 4; ++gs)
                    #pragma unroll
                    for (int nt = 0; nt < 4; ++nt) {
                        float2 v = *(const float2*)&xr[gs * 128 + n0w + nt * 8 + 2 * tq];
                        acc[gs][mt][nt][2 * hh]     = v.x;
                        acc[gs][mt][nt][2 * hh + 1] = v.y;
                    }
            }

        if (t > 0) {
            #pragma unroll
            for (int gp = 0; gp < 2; ++gp) {
                __syncthreads();   // w_s reads done; h_s writes from prev step visible
                stage_chunk(g_whh32, w_s,          2 * gp,     tid);
                stage_chunk(g_whh32, w_s + WCHUNK, 2 * gp + 1, tid);
                __syncthreads();
                gemm_2chunks(au, w_s, acc, gp, m0w, n0w, g, tq);
            }
        }

        // cell update (thread-local across the 4 gate chunks)
        #pragma unroll
        for (int mt = 0; mt < 2; ++mt)
            #pragma unroll
            for (int nt = 0; nt < 4; ++nt)
                #pragma unroll
                for (int q = 0; q < 4; ++q) {
                    float gi = acc[0][mt][nt][q];
                    float gf = acc[1][mt][nt][q];
                    float gg = acc[2][mt][nt][q];
                    float go = acc[3][mt][nt][q];
                    float cn = sigm_(gf) * c_st[mt][nt][q] + sigm_(gi) * tanh_(gg);
                    c_st[mt][nt][q] = cn;
                    hv[mt][nt][q]   = sigm_(go) * tanh_(cn);
                }

        if (t < FWW - 1) {
            __syncthreads();   // GEMM reads of h_s complete before rewrite
            #pragma unroll
            for (int mt = 0; mt < 2; ++mt)
                #pragma unroll
                for (int hh = 0; hh < 2; ++hh) {
                    int r = m0w + mt * 16 + g + 8 * hh;
                    #pragma unroll
                    for (int nt = 0; nt < 4; ++nt) {
                        float2 v = make_float2(f2tf(hv[mt][nt][2 * hh]), f2tf(hv[mt][nt][2 * hh + 1]));
                        *(float2*)&h_s[r * A_STRIDE + n0w + nt * 8 + 2 * tq] = v;
                    }
                }
        }
    }

    // store final h
    #pragma unroll
    for (int mt = 0; mt < 2; ++mt)
        #pragma unroll
        for (int hh = 0; hh < 2; ++hh) {
            int r  = m0w + mt * 16 + g + 8 * hh;
            int w_ = w0 + r;
            if (w_ < WW) {
                float* orow = g_hout + ((size_t)b * WW + w_) * HH;
                #pragma unroll
                for (int nt = 0; nt < 4; ++nt) {
                    float2 v = make_float2(hv[mt][nt][2 * hh], hv[mt][nt][2 * hh + 1]);
                    *(float2*)&orow[n0w + nt * 8 + 2 * tq] = v;
                }
            }
        }
}

// ---------------------------------------------------------------------------
// Kernel 3: max-pool over windows + FC
// ---------------------------------------------------------------------------
__global__ void pool_fc_kernel(const float* __restrict__ fc_w,
                               const float* __restrict__ fc_b,
                               float* __restrict__ out)
{
    __shared__ float red[256];
    __shared__ float feat[HH];
    const int b    = blockIdx.x;
    const int tid  = threadIdx.x;
    const int j    = tid & 127;
    const int half = tid >> 7;

    const float* base = g_hout + (size_t)b * WW * HH + j;
    float m = -3.4e38f;
    #pragma unroll 8
    for (int w = half; w < WW; w += 2) m = fmaxf(m, base[(size_t)w * HH]);
    red[tid] = m;
    __syncthreads();
    if (half == 0) feat[j] = fmaxf(red[j], red[j + 128]);
    __syncthreads();

    if (tid < 2) {
        float s = fc_b[tid];
        #pragma unroll 8
        for (int k = 0; k < HH; ++k) s += feat[k] * fc_w[tid * HH + k];
        out[b * 2 + tid] = s;
    }
}

// ---------------------------------------------------------------------------
extern "C" void kernel_launch(void* const* d_in, const int* in_sizes, int n_in,
                              void* d_out, int out_size)
{
    const int*   inputs = (const int*)  d_in[0];
    // d_in[1] = lengths : unused by the reference
    const float* embed  = (const float*)d_in[2];
    const float* w_ih   = (const float*)d_in[3];
    const float* w_hh   = (const float*)d_in[4];
    const float* b_ih   = (const float*)d_in[5];
    const float* b_hh   = (const float*)d_in[6];
    const float* fc_w   = (const float*)d_in[7];
    const float* fc_b   = (const float*)d_in[8];
    float* out = (float*)d_out;

    const size_t smem = (size_t)SMEM_FLOATS * sizeof(float);  // 164864 B

    static int inited = 0;
    cudaFuncSetAttribute(xproj_kernel, cudaFuncAttributeMaxDynamicSharedMemorySize, (int)smem);
    cudaFuncSetAttribute(lstm_kernel,  cudaFuncAttributeMaxDynamicSharedMemorySize, (int)smem);
    (void)inited;

    prep_kernel<<<64, 256>>>(w_ih, w_hh);
    xproj_kernel<<<NTOK / MT, NTHREADS, smem>>>(inputs, embed, b_ih, b_hh);
    lstm_kernel<<<dim3((WW + MT - 1) / MT, BB), NTHREADS, smem>>>();
    pool_fc_kernel<<<BB, 256>>>(fc_w, fc_b, out);
}

// round 3
// speedup vs baseline: 7.2141x; 2.6089x over previous
#include <cuda_runtime.h>
#include <cuda_bf16.h>
#include <math.h>

#define BB   64
#define SS   512
#define EE   128
#define HH   128
#define GG   512          // 4*H
#define FWW  6
#define WW   507          // S - FW + 1
#define NTOK (BB*SS)      // 32768
#define MT   64           // rows per CTA
#define NTHREADS 256
#define NTILES 8          // lstm window tiles (8*64 >= 507)

#define W_BYTES (GG*EE*2)        // 131072: resident bf16 weight (4 chunks of 128x128)
#define A_BYTES (MT*EE*2)        // 16384:  bf16 A tile, row stride 256B
#define SMEM_BYTES (W_BYTES + A_BYTES)

// Scratch (device globals: allocation is forbidden)
__device__ float g_xproj[(size_t)NTOK * GG];                 // 64 MB fp32
__device__ __align__(16) __nv_bfloat16 g_wih16[GG * EE];
__device__ __align__(16) __nv_bfloat16 g_whh16[GG * HH];
__device__ float g_featp[BB * NTILES * HH];

// ---------------------------------------------------------------------------
__device__ __forceinline__ unsigned sptr(const void* p) {
    return (unsigned)__cvta_generic_to_shared(p);
}
__device__ __forceinline__ float ex2f_(float x) { float y; asm("ex2.approx.f32 %0, %1;" : "=f"(y) : "f"(x)); return y; }
__device__ __forceinline__ float rcpf_(float x) { float y; asm("rcp.approx.f32 %0, %1;" : "=f"(y) : "f"(x)); return y; }
__device__ __forceinline__ float sigm_(float x) { return rcpf_(1.0f + ex2f_(-1.4426950408889634f * x)); }
__device__ __forceinline__ float tanh_(float x) {
    float e = ex2f_(2.8853900817779268f * x);
    return fmaf(-2.0f, rcpf_(e + 1.0f), 1.0f);
}
__device__ __forceinline__ void ldsm4(unsigned* r, unsigned addr) {
    asm volatile("ldmatrix.sync.aligned.m8n8.x4.shared.b16 {%0,%1,%2,%3}, [%4];"
                 : "=r"(r[0]), "=r"(r[1]), "=r"(r[2]), "=r"(r[3]) : "r"(addr));
}
__device__ __forceinline__ void mma_bf16(float* d, const unsigned* a, unsigned b0, unsigned b1) {
    asm("mma.sync.aligned.m16n8k16.row.col.f32.bf16.bf16.f32 "
        "{%0,%1,%2,%3},{%4,%5,%6,%7},{%8,%9},{%0,%1,%2,%3};"
        : "+f"(d[0]), "+f"(d[1]), "+f"(d[2]), "+f"(d[3])
        : "r"(a[0]), "r"(a[1]), "r"(a[2]), "r"(a[3]), "r"(b0), "r"(b1));
}
__device__ __forceinline__ unsigned packbf2(float lo, float hi) {
    __nv_bfloat162 p = __float22bfloat162_rn(make_float2(lo, hi));
    return *reinterpret_cast<unsigned*>(&p);
}

// ---------------------------------------------------------------------------
// Kernel 0: weights fp32 -> bf16 (layout [gate n][k], k contiguous)
// ---------------------------------------------------------------------------
__global__ void prep_kernel(const float* __restrict__ w_ih, const float* __restrict__ w_hh) {
    int i = blockIdx.x * blockDim.x + threadIdx.x;
    if (i < GG * EE) {
        g_wih16[i] = __float2bfloat16(w_ih[i]);
        g_whh16[i] = __float2bfloat16(w_hh[i]);
    }
}

// ---------------------------------------------------------------------------
// Stage a full 512x128 bf16 weight matrix into smem, 16B-chunk swizzled:
//   dst chunk (gs, n, c^(n&7)) = src chunk (gs, n, c);  8192 chunks, 32/thread
// ---------------------------------------------------------------------------
__device__ __forceinline__ void stage_w(const __nv_bfloat16* __restrict__ src, char* w_sc, int tid) {
    const uint4* s = (const uint4*)src;
    uint4* d = (uint4*)w_sc;
    #pragma unroll
    for (int i = 0; i < 32; ++i) {
        int id  = i * 256 + tid;
        int gs  = id >> 11;
        int rem = id & 2047;
        int n   = rem >> 4;
        int c   = rem & 15;
        d[gs * 2048 + n * 16 + (c ^ (n & 7))] = s[id];
    }
}

// ---------------------------------------------------------------------------
// Core GEMM: acc[gs][mt][nt] += A(64x128 bf16, smem) x Bchunk_gs^T (128x128 bf16, smem)
// Warp grid 2m x 4n; per warp M32, 32 cols per 128-col chunk. ldmatrix everywhere.
// ---------------------------------------------------------------------------
__device__ __forceinline__ void gemm_tile(unsigned aBase0, unsigned aBase1,
                                          unsigned bBase0,
                                          int rs, int qb, int qh,
                                          float acc[4][2][4][4]) {
    #pragma unroll
    for (int ks = 0; ks < 8; ++ks) {
        unsigned af0[4], af1[4];
        unsigned ca = ((unsigned)((2 * ks + qh) ^ rs)) << 4;
        ldsm4(af0, aBase0 + ca);
        ldsm4(af1, aBase1 + ca);
        unsigned cb = ((unsigned)((2 * ks + qb) ^ rs)) << 4;
        #pragma unroll
        for (int gs = 0; gs < 4; ++gs) {
            #pragma unroll
            for (int ntp = 0; ntp < 2; ++ntp) {
                unsigned bf[4];
                ldsm4(bf, bBase0 + ntp * 4096 + (gs << 15) + cb);
                mma_bf16(acc[gs][0][2 * ntp],     af0, bf[0], bf[1]);
                mma_bf16(acc[gs][0][2 * ntp + 1], af0, bf[2], bf[3]);
                mma_bf16(acc[gs][1][2 * ntp],     af1, bf[0], bf[1]);
                mma_bf16(acc[gs][1][2 * ntp + 1], af1, bf[2], bf[3]);
            }
        }
    }
}

// ---------------------------------------------------------------------------
// Kernel 1: xproj = emb . w_ih^T + b_ih + b_hh   (fp32 out)
// ---------------------------------------------------------------------------
__global__ __launch_bounds__(NTHREADS, 1)
void xproj_kernel(const int* __restrict__ inputs,
                  const float* __restrict__ embed,
                  const float* __restrict__ b_ih,
                  const float* __restrict__ b_hh)
{
    extern __shared__ char smem[];
    char* w_sc = smem;
    char* a_sc = smem + W_BYTES;

    const int tid  = threadIdx.x;
    const int lane = tid & 31;
    const int wid  = tid >> 5;
    const int g    = lane >> 2;
    const int tq   = lane & 3;
    const int rs   = lane & 7;
    const int qb   = (lane >> 3) & 1;
    const int qh   = (lane >> 4) & 1;
    const int m0w  = (wid >> 2) * 32;
    const int n0w  = (wid & 3) * 32;
    const int t0   = blockIdx.x * MT;

    stage_w(g_wih16, w_sc, tid);

    // gather embeddings -> bf16 swizzled A tile
    {
        int r = tid >> 2, th = tid & 3;
        const float4* erow = (const float4*)(embed + (size_t)inputs[t0 + r] * EE) + th * 8;
        #pragma unroll
        for (int j = 0; j < 4; ++j) {
            float4 v0 = erow[2 * j], v1 = erow[2 * j + 1];
            uint4 u;
            u.x = packbf2(v0.x, v0.y); u.y = packbf2(v0.z, v0.w);
            u.z = packbf2(v1.x, v1.y); u.w = packbf2(v1.z, v1.w);
            int c = th * 4 + j;
            *(uint4*)(a_sc + r * 256 + ((c ^ (r & 7)) << 4)) = u;
        }
    }
    __syncthreads();

    float acc[4][2][4][4];
    #pragma unroll
    for (int gs = 0; gs < 4; ++gs)
        #pragma unroll
        for (int nt = 0; nt < 4; ++nt) {
            int col = gs * 128 + n0w + nt * 8 + 2 * tq;
            float2 bi = *(const float2*)&b_ih[col];
            float2 bh = *(const float2*)&b_hh[col];
            float bx = bi.x + bh.x, by = bi.y + bh.y;
            #pragma unroll
            for (int mt = 0; mt < 2; ++mt) {
                acc[gs][mt][nt][0] = bx; acc[gs][mt][nt][1] = by;
                acc[gs][mt][nt][2] = bx; acc[gs][mt][nt][3] = by;
            }
        }

    unsigned aS = sptr(a_sc), wS = sptr(w_sc);
    unsigned aBase0 = aS + (m0w + rs + 8 * qb) * 256;
    unsigned aBase1 = aBase0 + 16 * 256;
    unsigned bBase0 = wS + (n0w + rs + 8 * qh) * 256;
    gemm_tile(aBase0, aBase1, bBase0, rs, qb, qh, acc);

    #pragma unroll
    for (int gs = 0; gs < 4; ++gs)
        #pragma unroll
        for (int mt = 0; mt < 2; ++mt)
            #pragma unroll
            for (int hh = 0; hh < 2; ++hh) {
                int r = m0w + mt * 16 + g + 8 * hh;
                float* orow = g_xproj + (size_t)(t0 + r) * GG;
                #pragma unroll
                for (int nt = 0; nt < 4; ++nt) {
                    float2 v = make_float2(acc[gs][mt][nt][2 * hh], acc[gs][mt][nt][2 * hh + 1]);
                    *(float2*)&orow[gs * 128 + n0w + nt * 8 + 2 * tq] = v;
                }
            }
}

// ---------------------------------------------------------------------------
// Kernel 2: 6-step LSTM + fused window max-pool
// ---------------------------------------------------------------------------
__global__ __launch_bounds__(NTHREADS, 1)
void lstm_kernel()
{
    extern __shared__ char smem[];
    char* w_sc = smem;            // resident w_hh (bf16, swizzled)
    char* a_sc = smem + W_BYTES;  // h tile (bf16, swizzled)

    const int tid  = threadIdx.x;
    const int lane = tid & 31;
    const int wid  = tid >> 5;
    const int g    = lane >> 2;
    const int tq   = lane & 3;
    const int rs   = lane & 7;
    const int qb   = (lane >> 3) & 1;
    const int qh   = (lane >> 4) & 1;
    const int m0w  = (wid >> 2) * 32;
    const int n0w  = (wid & 3) * 32;

    const int b  = blockIdx.y;
    const int w0 = blockIdx.x * MT;
    const int tokbase = b * SS;

    stage_w(g_whh16, w_sc, tid);

    int wv[2][2];
    #pragma unroll
    for (int mt = 0; mt < 2; ++mt)
        #pragma unroll
        for (int hh = 0; hh < 2; ++hh) {
            int w_ = w0 + m0w + mt * 16 + g + 8 * hh;
            wv[mt][hh] = (w_ < WW) ? w_ : (WW - 1);
        }

    float c_st[2][4][4];
    #pragma unroll
    for (int mt = 0; mt < 2; ++mt)
        #pragma unroll
        for (int nt = 0; nt < 4; ++nt)
            #pragma unroll
            for (int q = 0; q < 4; ++q) c_st[mt][nt][q] = 0.0f;

    float pmax[4][2];
    #pragma unroll
    for (int nt = 0; nt < 4; ++nt) { pmax[nt][0] = -3.4e38f; pmax[nt][1] = -3.4e38f; }

    unsigned aS = sptr(a_sc), wS = sptr(w_sc);
    unsigned aBase0 = aS + (m0w + rs + 8 * qb) * 256;
    unsigned aBase1 = aBase0 + 16 * 256;
    unsigned bBase0 = wS + (n0w + rs + 8 * qh) * 256;

    __syncthreads();   // staged weights visible

    for (int t = 0; t < FWW; ++t) {
        float acc[4][2][4][4];
        #pragma unroll
        for (int mt = 0; mt < 2; ++mt)
            #pragma unroll
            for (int hh = 0; hh < 2; ++hh) {
                const float* xr = g_xproj + (size_t)(tokbase + wv[mt][hh] + t) * GG;
                #pragma unroll
                for (int gs = 0; gs < 4; ++gs)
                    #pragma unroll
                    for (int nt = 0; nt < 4; ++nt) {
                        float2 v = *(const float2*)&xr[gs * 128 + n0w + nt * 8 + 2 * tq];
                        acc[gs][mt][nt][2 * hh]     = v.x;
                        acc[gs][mt][nt][2 * hh + 1] = v.y;
                    }
            }

        if (t > 0)
            gemm_tile(aBase0, aBase1, bBase0, rs, qb, qh, acc);

        __syncthreads();   // all h reads (ldsm) done before rewrite

        const bool last = (t == FWW - 1);
        #pragma unroll
        for (int mt = 0; mt < 2; ++mt)
            #pragma unroll
            for (int nt = 0; nt < 4; ++nt)
                #pragma unroll
                for (int hh = 0; hh < 2; ++hh) {
                    float h0, h1;
                    {
                        float gi = acc[0][mt][nt][2 * hh],     gf = acc[1][mt][nt][2 * hh];
                        float gg = acc[2][mt][nt][2 * hh],     go = acc[3][mt][nt][2 * hh];
                        float cn = sigm_(gf) * c_st[mt][nt][2 * hh] + sigm_(gi) * tanh_(gg);
                        c_st[mt][nt][2 * hh] = cn;
                        h0 = sigm_(go) * tanh_(cn);
                    }
                    {
                        float gi = acc[0][mt][nt][2 * hh + 1], gf = acc[1][mt][nt][2 * hh + 1];
                        float gg = acc[2][mt][nt][2 * hh + 1], go = acc[3][mt][nt][2 * hh + 1];
                        float cn = sigm_(gf) * c_st[mt][nt][2 * hh + 1] + sigm_(gi) * tanh_(gg);
                        c_st[mt][nt][2 * hh + 1] = cn;
                        h1 = sigm_(go) * tanh_(cn);
                    }
                    if (!last) {
                        int cb0 = (n0w >> 3) + nt;
                        int r   = m0w + mt * 16 + g + 8 * hh;
                        *(unsigned*)(a_sc + r * 256 + ((cb0 ^ g) << 4) + 4 * tq) = packbf2(h0, h1);
                    } else {
                        pmax[nt][0] = fmaxf(pmax[nt][0], h0);
                        pmax[nt][1] = fmaxf(pmax[nt][1], h1);
                    }
                }

        __syncthreads();   // new h visible before next step's ldsm
    }

    // fused pool: reduce pmax across the 16 threads sharing each h-column
    float* scr = (float*)w_sc;               // [128][17] overlay (w_s no longer read)
    const int slot = (wid >> 2) * 8 + g;
    #pragma unroll
    for (int nt = 0; nt < 4; ++nt)
        #pragma unroll
        for (int e = 0; e < 2; ++e)
            scr[(n0w + nt * 8 + 2 * tq + e) * 17 + slot] = pmax[nt][e];
    __syncthreads();
    if (tid < HH) {
        float m = scr[tid * 17];
        #pragma unroll
        for (int s = 1; s < 16; ++s) m = fmaxf(m, scr[tid * 17 + s]);
        g_featp[(b * NTILES + blockIdx.x) * HH + tid] = m;
    }
}

// ---------------------------------------------------------------------------
// Kernel 3: combine tile maxes + FC
// ---------------------------------------------------------------------------
__global__ void pool_fc_kernel(const float* __restrict__ fc_w,
                               const float* __restrict__ fc_b,
                               float* __restrict__ out)
{
    __shared__ float feat[HH];
    const int b = blockIdx.x, tid = threadIdx.x;   // 128 threads
    float m = g_featp[(b * NTILES) * HH + tid];
    #pragma unroll
    for (int s = 1; s < NTILES; ++s) m = fmaxf(m, g_featp[(b * NTILES + s) * HH + tid]);
    feat[tid] = m;
    __syncthreads();
    if (tid < 2) {
        float s = fc_b[tid];
        #pragma unroll 8
        for (int k = 0; k < HH; ++k) s += feat[k] * fc_w[tid * HH + k];
        out[b * 2 + tid] = s;
    }
}

// ---------------------------------------------------------------------------
extern "C" void kernel_launch(void* const* d_in, const int* in_sizes, int n_in,
                              void* d_out, int out_size)
{
    const int*   inputs = (const int*)  d_in[0];
    // d_in[1] = lengths : unused by the reference
    const float* embed  = (const float*)d_in[2];
    const float* w_ih   = (const float*)d_in[3];
    const float* w_hh   = (const float*)d_in[4];
    const float* b_ih   = (const float*)d_in[5];
    const float* b_hh   = (const float*)d_in[6];
    const float* fc_w   = (const float*)d_in[7];
    const float* fc_b   = (const float*)d_in[8];
    float* out = (float*)d_out;

    cudaFuncSetAttribute(xproj_kernel, cudaFuncAttributeMaxDynamicSharedMemorySize, SMEM_BYTES);
    cudaFuncSetAttribute(lstm_kernel,  cudaFuncAttributeMaxDynamicSharedMemorySize, SMEM_BYTES);

    prep_kernel<<<(GG * EE + 255) / 256, 256>>>(w_ih, w_hh);
    xproj_kernel<<<NTOK / MT, NTHREADS, SMEM_BYTES>>>(inputs, embed, b_ih, b_hh);
    lstm_kernel<<<dim3(NTILES, BB), NTHREADS, SMEM_BYTES>>>();
    pool_fc_kernel<<<BB, HH>>>(fc_w, fc_b, out);
}

// round 4
// speedup vs baseline: 8.1584x; 1.1309x over previous
#include <cuda_runtime.h>
#include <cuda_bf16.h>
#include <math.h>

#define BB   64
#define SS   512
#define EE   128
#define HH   128
#define GG   512          // 4*H
#define FWW  6
#define WW   507          // S - FW + 1
#define NTOK (BB*SS)      // 32768
#define MT   64           // rows per CTA
#define NTHREADS 256
#define NTILES 8          // lstm window tiles (8*64 >= 507)

#define W_BYTES (GG*EE*2)        // 131072: resident bf16 weight (4 chunks of 128x128)
#define A_BYTES (MT*EE*2)        // 16384:  bf16 A tile, row stride 256B
#define SMEM_BYTES (W_BYTES + A_BYTES)

// Scratch (device globals: allocation is forbidden)
__device__ __align__(16) __nv_bfloat16 g_xproj[(size_t)NTOK * GG];   // 32 MB bf16
__device__ __align__(16) __nv_bfloat16 g_wih16[GG * EE];
__device__ __align__(16) __nv_bfloat16 g_whh16[GG * HH];
__device__ unsigned g_featu[BB * HH];   // order-encoded float for atomicMax pooling

// ---------------------------------------------------------------------------
__device__ __forceinline__ unsigned sptr(const void* p) {
    return (unsigned)__cvta_generic_to_shared(p);
}
__device__ __forceinline__ float tanha_(float x) {
    float y; asm("tanh.approx.f32 %0, %1;" : "=f"(y) : "f"(x)); return y;
}
__device__ __forceinline__ float sigm_(float x) {
    return fmaf(0.5f, tanha_(0.5f * x), 0.5f);
}
__device__ __forceinline__ unsigned encf_(float x) {
    unsigned u = __float_as_uint(x);
    return (u & 0x80000000u) ? ~u : (u | 0x80000000u);
}
__device__ __forceinline__ float decf_(unsigned k) {
    return __uint_as_float((k & 0x80000000u) ? (k & 0x7fffffffu) : ~k);
}
__device__ __forceinline__ void ldsm4(unsigned* r, unsigned addr) {
    asm volatile("ldmatrix.sync.aligned.m8n8.x4.shared.b16 {%0,%1,%2,%3}, [%4];"
                 : "=r"(r[0]), "=r"(r[1]), "=r"(r[2]), "=r"(r[3]) : "r"(addr));
}
__device__ __forceinline__ void mma_bf16(float* d, const unsigned* a, unsigned b0, unsigned b1) {
    asm("mma.sync.aligned.m16n8k16.row.col.f32.bf16.bf16.f32 "
        "{%0,%1,%2,%3},{%4,%5,%6,%7},{%8,%9},{%0,%1,%2,%3};"
        : "+f"(d[0]), "+f"(d[1]), "+f"(d[2]), "+f"(d[3])
        : "r"(a[0]), "r"(a[1]), "r"(a[2]), "r"(a[3]), "r"(b0), "r"(b1));
}
__device__ __forceinline__ unsigned packbf2(float lo, float hi) {
    __nv_bfloat162 p = __float22bfloat162_rn(make_float2(lo, hi));
    return *reinterpret_cast<unsigned*>(&p);
}
__device__ __forceinline__ float2 unpackbf2(unsigned u) {
    return __bfloat1622float2(*reinterpret_cast<__nv_bfloat162*>(&u));
}

// ---------------------------------------------------------------------------
// Kernel 0: weights fp32 -> bf16; reset pooling accumulators
// ---------------------------------------------------------------------------
__global__ void prep_kernel(const float* __restrict__ w_ih, const float* __restrict__ w_hh) {
    int i = blockIdx.x * blockDim.x + threadIdx.x;
    if (i < GG * EE) {
        g_wih16[i] = __float2bfloat16(w_ih[i]);
        g_whh16[i] = __float2bfloat16(w_hh[i]);
    }
    if (i < BB * HH) g_featu[i] = 0u;   // below every encoded real float
}

// ---------------------------------------------------------------------------
// Stage a full 512x128 bf16 weight matrix into smem, 16B-chunk swizzled
// ---------------------------------------------------------------------------
__device__ __forceinline__ void stage_w(const __nv_bfloat16* __restrict__ src, char* w_sc, int tid) {
    const uint4* s = (const uint4*)src;
    uint4* d = (uint4*)w_sc;
    #pragma unroll
    for (int i = 0; i < 32; ++i) {
        int id  = i * 256 + tid;
        int gs  = id >> 11;
        int rem = id & 2047;
        int n   = rem >> 4;
        int c   = rem & 15;
        d[gs * 2048 + n * 16 + (c ^ (n & 7))] = s[id];
    }
}

// ---------------------------------------------------------------------------
// Core GEMM: acc[gs][mt][nt] += A(64x128) x Bchunk_gs^T (128x128), bf16/ldsm
// ---------------------------------------------------------------------------
__device__ __forceinline__ void gemm_tile(unsigned aBase0, unsigned aBase1,
                                          unsigned bBase0,
                                          int rs, int qb, int qh,
                                          float acc[4][2][4][4]) {
    #pragma unroll
    for (int ks = 0; ks < 8; ++ks) {
        unsigned af0[4], af1[4];
        unsigned ca = ((unsigned)((2 * ks + qh) ^ rs)) << 4;
        ldsm4(af0, aBase0 + ca);
        ldsm4(af1, aBase1 + ca);
        unsigned cb = ((unsigned)((2 * ks + qb) ^ rs)) << 4;
        #pragma unroll
        for (int gs = 0; gs < 4; ++gs) {
            #pragma unroll
            for (int ntp = 0; ntp < 2; ++ntp) {
                unsigned bf[4];
                ldsm4(bf, bBase0 + ntp * 4096 + (gs << 15) + cb);
                mma_bf16(acc[gs][0][2 * ntp],     af0, bf[0], bf[1]);
                mma_bf16(acc[gs][0][2 * ntp + 1], af0, bf[2], bf[3]);
                mma_bf16(acc[gs][1][2 * ntp],     af1, bf[0], bf[1]);
                mma_bf16(acc[gs][1][2 * ntp + 1], af1, bf[2], bf[3]);
            }
        }
    }
}

// ---------------------------------------------------------------------------
// Kernel 1: xproj = emb . w_ih^T + b_ih + b_hh   (bf16 out)
// ---------------------------------------------------------------------------
__global__ __launch_bounds__(NTHREADS, 1)
void xproj_kernel(const int* __restrict__ inputs,
                  const float* __restrict__ embed,
                  const float* __restrict__ b_ih,
                  const float* __restrict__ b_hh)
{
    extern __shared__ char smem[];
    char* w_sc = smem;
    char* a_sc = smem + W_BYTES;

    const int tid  = threadIdx.x;
    const int lane = tid & 31;
    const int wid  = tid >> 5;
    const int g    = lane >> 2;
    const int tq   = lane & 3;
    const int rs   = lane & 7;
    const int qb   = (lane >> 3) & 1;
    const int qh   = (lane >> 4) & 1;
    const int m0w  = (wid >> 2) * 32;
    const int n0w  = (wid & 3) * 32;
    const int t0   = blockIdx.x * MT;

    stage_w(g_wih16, w_sc, tid);

    // gather embeddings -> bf16 swizzled A tile
    {
        int r = tid >> 2, th = tid & 3;
        const float4* erow = (const float4*)(embed + (size_t)inputs[t0 + r] * EE) + th * 8;
        #pragma unroll
        for (int j = 0; j < 4; ++j) {
            float4 v0 = erow[2 * j], v1 = erow[2 * j + 1];
            uint4 u;
            u.x = packbf2(v0.x, v0.y); u.y = packbf2(v0.z, v0.w);
            u.z = packbf2(v1.x, v1.y); u.w = packbf2(v1.z, v1.w);
            int c = th * 4 + j;
            *(uint4*)(a_sc + r * 256 + ((c ^ (r & 7)) << 4)) = u;
        }
    }
    __syncthreads();

    float acc[4][2][4][4];
    #pragma unroll
    for (int gs = 0; gs < 4; ++gs)
        #pragma unroll
        for (int nt = 0; nt < 4; ++nt) {
            int col = gs * 128 + n0w + nt * 8 + 2 * tq;
            float2 bi = *(const float2*)&b_ih[col];
            float2 bh = *(const float2*)&b_hh[col];
            float bx = bi.x + bh.x, by = bi.y + bh.y;
            #pragma unroll
            for (int mt = 0; mt < 2; ++mt) {
                acc[gs][mt][nt][0] = bx; acc[gs][mt][nt][1] = by;
                acc[gs][mt][nt][2] = bx; acc[gs][mt][nt][3] = by;
            }
        }

    unsigned aS = sptr(a_sc), wS = sptr(w_sc);
    unsigned aBase0 = aS + (m0w + rs + 8 * qb) * 256;
    unsigned aBase1 = aBase0 + 16 * 256;
    unsigned bBase0 = wS + (n0w + rs + 8 * qh) * 256;
    gemm_tile(aBase0, aBase1, bBase0, rs, qb, qh, acc);

    #pragma unroll
    for (int gs = 0; gs < 4; ++gs)
        #pragma unroll
        for (int mt = 0; mt < 2; ++mt)
            #pragma unroll
            for (int hh = 0; hh < 2; ++hh) {
                int r = m0w + mt * 16 + g + 8 * hh;
                __nv_bfloat16* orow = g_xproj + (size_t)(t0 + r) * GG;
                #pragma unroll
                for (int nt = 0; nt < 4; ++nt) {
                    unsigned u = packbf2(acc[gs][mt][nt][2 * hh], acc[gs][mt][nt][2 * hh + 1]);
                    *(unsigned*)&orow[gs * 128 + n0w + nt * 8 + 2 * tq] = u;
                }
            }
}

// ---------------------------------------------------------------------------
// Kernel 2: 6-step LSTM + fused window max-pool (atomicMax into g_featu)
// ---------------------------------------------------------------------------
__global__ __launch_bounds__(NTHREADS, 1)
void lstm_kernel()
{
    extern __shared__ char smem[];
    char* w_sc = smem;            // resident w_hh (bf16, swizzled)
    char* a_sc = smem + W_BYTES;  // h tile (bf16, swizzled)

    const int tid  = threadIdx.x;
    const int lane = tid & 31;
    const int wid  = tid >> 5;
    const int g    = lane >> 2;
    const int tq   = lane & 3;
    const int rs   = lane & 7;
    const int qb   = (lane >> 3) & 1;
    const int qh   = (lane >> 4) & 1;
    const int m0w  = (wid >> 2) * 32;
    const int n0w  = (wid & 3) * 32;

    const int b  = blockIdx.y;
    const int w0 = blockIdx.x * MT;
    const int tokbase = b * SS;

    stage_w(g_whh16, w_sc, tid);

    int wv[2][2];
    #pragma unroll
    for (int mt = 0; mt < 2; ++mt)
        #pragma unroll
        for (int hh = 0; hh < 2; ++hh) {
            int w_ = w0 + m0w + mt * 16 + g + 8 * hh;
            wv[mt][hh] = (w_ < WW) ? w_ : (WW - 1);
        }

    float c_st[2][4][4];
    #pragma unroll
    for (int mt = 0; mt < 2; ++mt)
        #pragma unroll
        for (int nt = 0; nt < 4; ++nt)
            #pragma unroll
            for (int q = 0; q < 4; ++q) c_st[mt][nt][q] = 0.0f;

    float pmax[4][2];
    #pragma unroll
    for (int nt = 0; nt < 4; ++nt) { pmax[nt][0] = -3.4e38f; pmax[nt][1] = -3.4e38f; }

    unsigned aS = sptr(a_sc), wS = sptr(w_sc);
    unsigned aBase0 = aS + (m0w + rs + 8 * qb) * 256;
    unsigned aBase1 = aBase0 + 16 * 256;
    unsigned bBase0 = wS + (n0w + rs + 8 * qh) * 256;

    __syncthreads();   // staged weights visible

    for (int t = 0; t < FWW; ++t) {
        float acc[4][2][4][4];
        #pragma unroll
        for (int mt = 0; mt < 2; ++mt)
            #pragma unroll
            for (int hh = 0; hh < 2; ++hh) {
                const __nv_bfloat16* xr = g_xproj + (size_t)(tokbase + wv[mt][hh] + t) * GG;
                #pragma unroll
                for (int gs = 0; gs < 4; ++gs)
                    #pragma unroll
                    for (int nt = 0; nt < 4; ++nt) {
                        unsigned u = *(const unsigned*)&xr[gs * 128 + n0w + nt * 8 + 2 * tq];
                        float2 v = unpackbf2(u);
                        acc[gs][mt][nt][2 * hh]     = v.x;
                        acc[gs][mt][nt][2 * hh + 1] = v.y;
                    }
            }

        if (t > 0)
            gemm_tile(aBase0, aBase1, bBase0, rs, qb, qh, acc);

        __syncthreads();   // all h reads (ldsm) done before rewrite

        const bool last = (t == FWW - 1);
        #pragma unroll
        for (int mt = 0; mt < 2; ++mt)
            #pragma unroll
            for (int nt = 0; nt < 4; ++nt)
                #pragma unroll
                for (int hh = 0; hh < 2; ++hh) {
                    float h0, h1;
                    {
                        float gi = acc[0][mt][nt][2 * hh],     gf = acc[1][mt][nt][2 * hh];
                        float gg = acc[2][mt][nt][2 * hh],     go = acc[3][mt][nt][2 * hh];
                        float cn = sigm_(gf) * c_st[mt][nt][2 * hh] + sigm_(gi) * tanha_(gg);
                        c_st[mt][nt][2 * hh] = cn;
                        h0 = sigm_(go) * tanha_(cn);
                    }
                    {
                        float gi = acc[0][mt][nt][2 * hh + 1], gf = acc[1][mt][nt][2 * hh + 1];
                        float gg = acc[2][mt][nt][2 * hh + 1], go = acc[3][mt][nt][2 * hh + 1];
                        float cn = sigm_(gf) * c_st[mt][nt][2 * hh + 1] + sigm_(gi) * tanha_(gg);
                        c_st[mt][nt][2 * hh + 1] = cn;
                        h1 = sigm_(go) * tanha_(cn);
                    }
                    if (!last) {
                        int cb0 = (n0w >> 3) + nt;
                        int r   = m0w + mt * 16 + g + 8 * hh;
                        *(unsigned*)(a_sc + r * 256 + ((cb0 ^ g) << 4) + 4 * tq) = packbf2(h0, h1);
                    } else {
                        pmax[nt][0] = fmaxf(pmax[nt][0], h0);
                        pmax[nt][1] = fmaxf(pmax[nt][1], h1);
                    }
                }

        __syncthreads();   // new h visible before next step's ldsm
    }

    // per-CTA pool reduction (16 threads share each h-column), then one atomic each
    float* scr = (float*)w_sc;               // [128][17] overlay (w_s no longer read)
    const int slot = (wid >> 2) * 8 + g;
    #pragma unroll
    for (int nt = 0; nt < 4; ++nt)
        #pragma unroll
        for (int e = 0; e < 2; ++e)
            scr[(n0w + nt * 8 + 2 * tq + e) * 17 + slot] = pmax[nt][e];
    __syncthreads();
    if (tid < HH) {
        float m = scr[tid * 17];
        #pragma unroll
        for (int s = 1; s < 16; ++s) m = fmaxf(m, scr[tid * 17 + s]);
        atomicMax(&g_featu[b * HH + tid], encf_(m));
    }
}

// ---------------------------------------------------------------------------
// Kernel 3: decode pooled features + FC
// ---------------------------------------------------------------------------
__global__ void pool_fc_kernel(const float* __restrict__ fc_w,
                               const float* __restrict__ fc_b,
                               float* __restrict__ out)
{
    __shared__ float feat[HH];
    const int b = blockIdx.x, tid = threadIdx.x;   // 128 threads
    feat[tid] = decf_(g_featu[b * HH + tid]);
    __syncthreads();
    if (tid < 2) {
        float s = fc_b[tid];
        #pragma unroll 8
        for (int k = 0; k < HH; ++k) s += feat[k] * fc_w[tid * HH + k];
        out[b * 2 + tid] = s;
    }
}

// ---------------------------------------------------------------------------
extern "C" void kernel_launch(void* const* d_in, const int* in_sizes, int n_in,
                              void* d_out, int out_size)
{
    const int*   inputs = (const int*)  d_in[0];
    // d_in[1] = lengths : unused by the reference
    const float* embed  = (const float*)d_in[2];
    const float* w_ih   = (const float*)d_in[3];
    const float* w_hh   = (const float*)d_in[4];
    const float* b_ih   = (const float*)d_in[5];
    const float* b_hh   = (const float*)d_in[6];
    const float* fc_w   = (const float*)d_in[7];
    const float* fc_b   = (const float*)d_in[8];
    float* out = (float*)d_out;

    cudaFuncSetAttribute(xproj_kernel, cudaFuncAttributeMaxDynamicSharedMemorySize, SMEM_BYTES);
    cudaFuncSetAttribute(lstm_kernel,  cudaFuncAttributeMaxDynamicSharedMemorySize, SMEM_BYTES);

    prep_kernel<<<(GG * EE + 255) / 256, 256>>>(w_ih, w_hh);
    xproj_kernel<<<NTOK / MT, NTHREADS, SMEM_BYTES>>>(inputs, embed, b_ih, b_hh);
    lstm_kernel<<<dim3(NTILES, BB), NTHREADS, SMEM_BYTES>>>();
    pool_fc_kernel<<<BB, HH>>>(fc_w, fc_b, out);
}

// round 5
// speedup vs baseline: 9.6389x; 1.1815x over previous
#include <cuda_runtime.h>
#include <cuda_bf16.h>
#include <math.h>

#define BB   64
#define SS   512
#define EE   128
#define HH   128
#define GG   512          // 4*H
#define FWW  6
#define WW   507          // S - FW + 1
#define NTOK (BB*SS)      // 32768
#define MT   64           // rows per CTA tile
#define NTHREADS 256
#define NTILES 8          // lstm window tiles (8*64 >= 507)
#define XP_TILES 4        // xproj tiles per CTA

#define W_BYTES (GG*EE*2)        // 131072: resident bf16 weight
#define A_BYTES (MT*EE*2)        // 16384:  bf16 A tile, row stride 256B
#define X_STRIDE 1040            // 512 bf16 row + 16B pad (bank stagger)
#define X_BYTES (MT*X_STRIDE)    // 66560: xproj prefetch buffer
#define SMEM_XP (W_BYTES + A_BYTES)
#define SMEM_LS (W_BYTES + A_BYTES + X_BYTES)   // 214016 < 227KB

// Scratch (device globals: allocation is forbidden)
__device__ __align__(16) __nv_bfloat16 g_xproj[(size_t)NTOK * GG];   // 32 MB bf16
__device__ __align__(16) __nv_bfloat16 g_wih16[GG * EE];
__device__ __align__(16) __nv_bfloat16 g_whh16[GG * HH];
__device__ unsigned g_featu[BB * HH];   // order-encoded float for atomicMax pooling

// ---------------------------------------------------------------------------
__device__ __forceinline__ unsigned sptr(const void* p) {
    return (unsigned)__cvta_generic_to_shared(p);
}
__device__ __forceinline__ float tanha_(float x) {
    float y; asm("tanh.approx.f32 %0, %1;" : "=f"(y) : "f"(x)); return y;
}
__device__ __forceinline__ float sigm_(float x) {
    return fmaf(0.5f, tanha_(0.5f * x), 0.5f);
}
__device__ __forceinline__ unsigned encf_(float x) {
    unsigned u = __float_as_uint(x);
    return (u & 0x80000000u) ? ~u : (u | 0x80000000u);
}
__device__ __forceinline__ float decf_(unsigned k) {
    return __uint_as_float((k & 0x80000000u) ? (k & 0x7fffffffu) : ~k);
}
__device__ __forceinline__ void ldsm4(unsigned* r, unsigned addr) {
    asm volatile("ldmatrix.sync.aligned.m8n8.x4.shared.b16 {%0,%1,%2,%3}, [%4];"
                 : "=r"(r[0]), "=r"(r[1]), "=r"(r[2]), "=r"(r[3]) : "r"(addr));
}
__device__ __forceinline__ void mma_bf16(float* d, const unsigned* a, unsigned b0, unsigned b1) {
    asm("mma.sync.aligned.m16n8k16.row.col.f32.bf16.bf16.f32 "
        "{%0,%1,%2,%3},{%4,%5,%6,%7},{%8,%9},{%0,%1,%2,%3};"
        : "+f"(d[0]), "+f"(d[1]), "+f"(d[2]), "+f"(d[3])
        : "r"(a[0]), "r"(a[1]), "r"(a[2]), "r"(a[3]), "r"(b0), "r"(b1));
}
__device__ __forceinline__ unsigned packbf2(float lo, float hi) {
    __nv_bfloat162 p = __float22bfloat162_rn(make_float2(lo, hi));
    return *reinterpret_cast<unsigned*>(&p);
}

// ---------------------------------------------------------------------------
// Kernel 0: weights fp32 -> bf16; reset pooling accumulators
// ---------------------------------------------------------------------------
__global__ void prep_kernel(const float* __restrict__ w_ih, const float* __restrict__ w_hh) {
    int i = blockIdx.x * blockDim.x + threadIdx.x;
    if (i < GG * EE) {
        g_wih16[i] = __float2bfloat16(w_ih[i]);
        g_whh16[i] = __float2bfloat16(w_hh[i]);
    }
    if (i < BB * HH) g_featu[i] = 0u;
}

// ---------------------------------------------------------------------------
// Stage a full 512x128 bf16 weight matrix into smem, 16B-chunk swizzled
// ---------------------------------------------------------------------------
__device__ __forceinline__ void stage_w(const __nv_bfloat16* __restrict__ src, char* w_sc, int tid) {
    const uint4* s = (const uint4*)src;
    uint4* d = (uint4*)w_sc;
    #pragma unroll
    for (int i = 0; i < 32; ++i) {
        int id  = i * 256 + tid;
        int gs  = id >> 11;
        int rem = id & 2047;
        int n   = rem >> 4;
        int c   = rem & 15;
        d[gs * 2048 + n * 16 + (c ^ (n & 7))] = s[id];
    }
}

// ---------------------------------------------------------------------------
// cp.async prefetch of one step's xproj rows into x_sc
// ---------------------------------------------------------------------------
__device__ __forceinline__ void prefetch_x(const __nv_bfloat16* __restrict__ xbase,
                                           int w0, int t, int tid, char* x_sc) {
    int r  = tid >> 2;                        // 0..63 (local row)
    int c0 = tid & 3;
    int tok = min(w0 + r, WW - 1) + t;        // matches reader's window clamp
    const char* src = (const char*)(xbase + (size_t)tok * GG);
    char* dstrow = x_sc + r * X_STRIDE;
    #pragma unroll
    for (int i = 0; i < 16; ++i) {
        int c = (c0 + 4 * i) * 16;
        unsigned daddr = sptr(dstrow + c);
        asm volatile("cp.async.cg.shared.global [%0], [%1], 16;" :: "r"(daddr), "l"(src + c));
    }
    asm volatile("cp.async.commit_group;");
}
__device__ __forceinline__ void cp_wait_all() {
    asm volatile("cp.async.wait_group 0;");
}

// ---------------------------------------------------------------------------
// Core GEMM: acc[gs][mt][nt] += A(64x128) x Bchunk_gs^T (128x128), bf16/ldsm
// ---------------------------------------------------------------------------
__device__ __forceinline__ void gemm_tile(unsigned aBase0, unsigned aBase1,
                                          unsigned bBase0,
                                          int rs, int qb, int qh,
                                          float acc[4][2][4][4]) {
    #pragma unroll
    for (int ks = 0; ks < 8; ++ks) {
        unsigned af0[4], af1[4];
        unsigned ca = ((unsigned)((2 * ks + qh) ^ rs)) << 4;
        ldsm4(af0, aBase0 + ca);
        ldsm4(af1, aBase1 + ca);
        unsigned cb = ((unsigned)((2 * ks + qb) ^ rs)) << 4;
        #pragma unroll
        for (int gs = 0; gs < 4; ++gs) {
            #pragma unroll
            for (int ntp = 0; ntp < 2; ++ntp) {
                unsigned bf[4];
                ldsm4(bf, bBase0 + ntp * 4096 + (gs << 15) + cb);
                mma_bf16(acc[gs][0][2 * ntp],     af0, bf[0], bf[1]);
                mma_bf16(acc[gs][0][2 * ntp + 1], af0, bf[2], bf[3]);
                mma_bf16(acc[gs][1][2 * ntp],     af1, bf[0], bf[1]);
                mma_bf16(acc[gs][1][2 * ntp + 1], af1, bf[2], bf[3]);
            }
        }
    }
}

// ---------------------------------------------------------------------------
// Kernel 1: xproj = emb . w_ih^T + b_ih + b_hh  (bf16 out); 4 tiles per CTA
// ---------------------------------------------------------------------------
__global__ __launch_bounds__(NTHREADS, 1)
void xproj_kernel(const int* __restrict__ inputs,
                  const float* __restrict__ embed,
                  const float* __restrict__ b_ih,
                  const float* __restrict__ b_hh)
{
    extern __shared__ char smem[];
    char* w_sc = smem;
    char* a_sc = smem + W_BYTES;

    const int tid  = threadIdx.x;
    const int lane = tid & 31;
    const int wid  = tid >> 5;
    const int g    = lane >> 2;
    const int tq   = lane & 3;
    const int rs   = lane & 7;
    const int qb   = (lane >> 3) & 1;
    const int qh   = (lane >> 4) & 1;
    const int m0w  = (wid >> 2) * 32;
    const int n0w  = (wid & 3) * 32;

    stage_w(g_wih16, w_sc, tid);

    // bias (hoisted)
    float bias[4][4][2];
    #pragma unroll
    for (int gs = 0; gs < 4; ++gs)
        #pragma unroll
        for (int nt = 0; nt < 4; ++nt) {
            int col = gs * 128 + n0w + nt * 8 + 2 * tq;
            float2 bi = *(const float2*)&b_ih[col];
            float2 bh = *(const float2*)&b_hh[col];
            bias[gs][nt][0] = bi.x + bh.x;
            bias[gs][nt][1] = bi.y + bh.y;
        }

    unsigned aS = sptr(a_sc), wS = sptr(w_sc);
    unsigned aBase0 = aS + (m0w + rs + 8 * qb) * 256;
    unsigned aBase1 = aBase0 + 16 * 256;
    unsigned bBase0 = wS + (n0w + rs + 8 * qh) * 256;

    for (int tile = 0; tile < XP_TILES; ++tile) {
        const int t0 = (blockIdx.x * XP_TILES + tile) * MT;
        __syncthreads();   // prev gemm's a_sc reads done (and stage_w at tile 0)
        {
            int r = tid >> 2, th = tid & 3;
            const float4* erow = (const float4*)(embed + (size_t)inputs[t0 + r] * EE) + th * 8;
            #pragma unroll
            for (int j = 0; j < 4; ++j) {
                float4 v0 = erow[2 * j], v1 = erow[2 * j + 1];
                uint4 u;
                u.x = packbf2(v0.x, v0.y); u.y = packbf2(v0.z, v0.w);
                u.z = packbf2(v1.x, v1.y); u.w = packbf2(v1.z, v1.w);
                int c = th * 4 + j;
                *(uint4*)(a_sc + r * 256 + ((c ^ (r & 7)) << 4)) = u;
            }
        }
        __syncthreads();

        float acc[4][2][4][4];
        #pragma unroll
        for (int gs = 0; gs < 4; ++gs)
            #pragma unroll
            for (int nt = 0; nt < 4; ++nt)
                #pragma unroll
                for (int mt = 0; mt < 2; ++mt) {
                    acc[gs][mt][nt][0] = bias[gs][nt][0]; acc[gs][mt][nt][1] = bias[gs][nt][1];
                    acc[gs][mt][nt][2] = bias[gs][nt][0]; acc[gs][mt][nt][3] = bias[gs][nt][1];
                }

        gemm_tile(aBase0, aBase1, bBase0, rs, qb, qh, acc);

        #pragma unroll
        for (int gs = 0; gs < 4; ++gs)
            #pragma unroll
            for (int mt = 0; mt < 2; ++mt)
                #pragma unroll
                for (int hh = 0; hh < 2; ++hh) {
                    int r = m0w + mt * 16 + g + 8 * hh;
                    __nv_bfloat16* orow = g_xproj + (size_t)(t0 + r) * GG;
                    #pragma unroll
                    for (int nt = 0; nt < 4; ++nt) {
                        unsigned u = packbf2(acc[gs][mt][nt][2 * hh], acc[gs][mt][nt][2 * hh + 1]);
                        *(unsigned*)&orow[gs * 128 + n0w + nt * 8 + 2 * tq] = u;
                    }
                }
    }
}

// ---------------------------------------------------------------------------
// Kernel 2: 6-step LSTM + fused pool; cp.async-pipelined xproj
// ---------------------------------------------------------------------------
__global__ __launch_bounds__(NTHREADS, 1)
void lstm_kernel()
{
    extern __shared__ char smem[];
    char* w_sc = smem;                       // resident w_hh (bf16, swizzled)
    char* a_sc = smem + W_BYTES;             // h tile (bf16, swizzled)
    char* x_sc = smem + W_BYTES + A_BYTES;   // prefetched xproj rows

    const int tid  = threadIdx.x;
    const int lane = tid & 31;
    const int wid  = tid >> 5;
    const int g    = lane >> 2;
    const int tq   = lane & 3;
    const int rs   = lane & 7;
    const int qb   = (lane >> 3) & 1;
    const int qh   = (lane >> 4) & 1;
    const int m0w  = (wid >> 2) * 32;
    const int n0w  = (wid & 3) * 32;

    const int b  = blockIdx.y;
    const int w0 = blockIdx.x * MT;
    const __nv_bfloat16* xbase = g_xproj + (size_t)b * SS * GG;

    stage_w(g_whh16, w_sc, tid);
    prefetch_x(xbase, w0, 0, tid, x_sc);

    float c_st[2][4][4];
    #pragma unroll
    for (int mt = 0; mt < 2; ++mt)
        #pragma unroll
        for (int nt = 0; nt < 4; ++nt)
            #pragma unroll
            for (int q = 0; q < 4; ++q) c_st[mt][nt][q] = 0.0f;

    float pmax[4][2];
    #pragma unroll
    for (int nt = 0; nt < 4; ++nt) { pmax[nt][0] = -3.4e38f; pmax[nt][1] = -3.4e38f; }

    unsigned aS = sptr(a_sc), wS = sptr(w_sc);
    unsigned aBase0 = aS + (m0w + rs + 8 * qb) * 256;
    unsigned aBase1 = aBase0 + 16 * 256;
    unsigned bBase0 = wS + (n0w + rs + 8 * qh) * 256;

    __syncthreads();   // staged weights visible

    for (int t = 0; t < FWW; ++t) {
        cp_wait_all();
        __syncthreads();   // X(t) complete everywhere; h(t-1) stores visible

        float acc[4][2][4][4];
        #pragma unroll
        for (int mt = 0; mt < 2; ++mt)
            #pragma unroll
            for (int hh = 0; hh < 2; ++hh) {
                int r = m0w + mt * 16 + g + 8 * hh;
                const char* xr = x_sc + r * X_STRIDE;
                #pragma unroll
                for (int gs = 0; gs < 4; ++gs)
                    #pragma unroll
                    for (int nt = 0; nt < 4; ++nt) {
                        unsigned u = *(const unsigned*)(xr + (gs * 128 + n0w + nt * 8 + 2 * tq) * 2);
                        __nv_bfloat162 p = *reinterpret_cast<__nv_bfloat162*>(&u);
                        float2 v = __bfloat1622float2(p);
                        acc[gs][mt][nt][2 * hh]     = v.x;
                        acc[gs][mt][nt][2 * hh + 1] = v.y;
                    }
            }

        if (t > 0)
            gemm_tile(aBase0, aBase1, bBase0, rs, qb, qh, acc);

        // cell update BEFORE barrier: register-only MUFU work, overlaps other
        // warps' MMA/LDSM tails
        float hreg[2][4][4];
        #pragma unroll
        for (int mt = 0; mt < 2; ++mt)
            #pragma unroll
            for (int nt = 0; nt < 4; ++nt)
                #pragma unroll
                for (int q = 0; q < 4; ++q) {
                    float gi = acc[0][mt][nt][q];
                    float gf = acc[1][mt][nt][q];
                    float gg = acc[2][mt][nt][q];
                    float go = acc[3][mt][nt][q];
                    float cn = sigm_(gf) * c_st[mt][nt][q] + sigm_(gi) * tanha_(gg);
                    c_st[mt][nt][q] = cn;
                    hreg[mt][nt][q] = sigm_(go) * tanha_(cn);
                }

        __syncthreads();   // all x_sc/a_sc/w_sc reads of this step done

        if (t < FWW - 1) {
            prefetch_x(xbase, w0, t + 1, tid, x_sc);   // fills X(t+1) during next barrier window
            #pragma unroll
            for (int mt = 0; mt < 2; ++mt)
                #pragma unroll
                for (int nt = 0; nt < 4; ++nt)
                    #pragma unroll
                    for (int hh = 0; hh < 2; ++hh) {
                        int cb0 = (n0w >> 3) + nt;
                        int r   = m0w + mt * 16 + g + 8 * hh;
                        *(unsigned*)(a_sc + r * 256 + ((cb0 ^ g) << 4) + 4 * tq) =
                            packbf2(hreg[mt][nt][2 * hh], hreg[mt][nt][2 * hh + 1]);
                    }
        } else {
            #pragma unroll
            for (int nt = 0; nt < 4; ++nt)
                #pragma unroll
                for (int mt = 0; mt < 2; ++mt)
                    #pragma unroll
                    for (int hh = 0; hh < 2; ++hh) {
                        pmax[nt][0] = fmaxf(pmax[nt][0], hreg[mt][nt][2 * hh]);
                        pmax[nt][1] = fmaxf(pmax[nt][1], hreg[mt][nt][2 * hh + 1]);
                    }
        }
    }

    // per-CTA pool reduction (16 threads share each h-column), then one atomic each
    float* scr = (float*)w_sc;               // overlay (w_s no longer read)
    const int slot = (wid >> 2) * 8 + g;
    #pragma unroll
    for (int nt = 0; nt < 4; ++nt)
        #pragma unroll
        for (int e = 0; e < 2; ++e)
            scr[(n0w + nt * 8 + 2 * tq + e) * 17 + slot] = pmax[nt][e];
    __syncthreads();
    if (tid < HH) {
        float m = scr[tid * 17];
        #pragma unroll
        for (int s = 1; s < 16; ++s) m = fmaxf(m, scr[tid * 17 + s]);
        atomicMax(&g_featu[b * HH + tid], encf_(m));
    }
}

// ---------------------------------------------------------------------------
// Kernel 3: decode pooled features + FC (parallel reduction)
// ---------------------------------------------------------------------------
__global__ void pool_fc_kernel(const float* __restrict__ fc_w,
                               const float* __restrict__ fc_b,
                               float* __restrict__ out)
{
    __shared__ float part[8];   // 4 warps x 2 outputs
    const int b = blockIdx.x, tid = threadIdx.x;   // 128 threads
    const int lane = tid & 31, wrp = tid >> 5;

    float f  = decf_(g_featu[b * HH + tid]);
    float p0 = f * fc_w[tid];
    float p1 = f * fc_w[HH + tid];
    #pragma unroll
    for (int o = 16; o > 0; o >>= 1) {
        p0 += __shfl_xor_sync(0xffffffffu, p0, o);
        p1 += __shfl_xor_sync(0xffffffffu, p1, o);
    }
    if (lane == 0) { part[wrp] = p0; part[4 + wrp] = p1; }
    __syncthreads();
    if (tid < 2) {
        float s = fc_b[tid] + part[4 * tid] + part[4 * tid + 1] + part[4 * tid + 2] + part[4 * tid + 3];
        out[b * 2 + tid] = s;
    }
}

// ---------------------------------------------------------------------------
extern "C" void kernel_launch(void* const* d_in, const int* in_sizes, int n_in,
                              void* d_out, int out_size)
{
    const int*   inputs = (const int*)  d_in[0];
    // d_in[1] = lengths : unused by the reference
    const float* embed  = (const float*)d_in[2];
    const float* w_ih   = (const float*)d_in[3];
    const float* w_hh   = (const float*)d_in[4];
    const float* b_ih   = (const float*)d_in[5];
    const float* b_hh   = (const float*)d_in[6];
    const float* fc_w   = (const float*)d_in[7];
    const float* fc_b   = (const float*)d_in[8];
    float* out = (float*)d_out;

    cudaFuncSetAttribute(xproj_kernel, cudaFuncAttributeMaxDynamicSharedMemorySize, SMEM_XP);
    cudaFuncSetAttribute(lstm_kernel,  cudaFuncAttributeMaxDynamicSharedMemorySize, SMEM_LS);

    prep_kernel<<<(GG * EE + 255) / 256, 256>>>(w_ih, w_hh);
    xproj_kernel<<<NTOK / (MT * XP_TILES), NTHREADS, SMEM_XP>>>(inputs, embed, b_ih, b_hh);
    lstm_kernel<<<dim3(NTILES, BB), NTHREADS, SMEM_LS>>>();
    pool_fc_kernel<<<BB, HH>>>(fc_w, fc_b, out);
}

// round 7
// speedup vs baseline: 9.9483x; 1.0321x over previous
#include <cuda_runtime.h>
#include <cuda_bf16.h>
#include <math.h>

#define BB   64
#define SS   512
#define EE   128
#define HH   128
#define GG   512          // 4*H
#define FWW  6
#define WW   507          // S - FW + 1
#define NTOK (BB*SS)      // 32768
#define MT   64           // rows per CTA (2 halves of 32)
#define NTHREADS 256
#define NTILES 8          // lstm window tiles (8*64 >= 507)
#define XP_TILES 4        // xproj tiles per CTA
#define NCTAS (NTILES*BB) // 512 lstm CTAs

#define W_BYTES (GG*EE*2)        // 131072: resident bf16 weight
#define A_BYTES (MT*EE*2)        // 16384:  bf16 h tile (2 halves of 8KB)
#define X_STRIDE 1040            // 512 bf16 row + 16B pad
#define X_BYTES (MT*X_STRIDE)    // 66560
#define SMEM_XP (W_BYTES + A_BYTES)
#define SMEM_LS (W_BYTES + A_BYTES + X_BYTES)   // 214016 < 227KB

// Scratch (device globals: allocation is forbidden)
__device__ __align__(16) __nv_bfloat16 g_xproj[(size_t)NTOK * GG];   // 32 MB
__device__ __align__(16) __nv_bfloat16 g_wih16[GG * EE];
__device__ __align__(16) __nv_bfloat16 g_whh16[GG * HH];
__device__ unsigned g_featu[BB * HH];   // order-encoded float, atomicMax pooling
__device__ unsigned g_done;             // CTA completion counter

// ---------------------------------------------------------------------------
__device__ __forceinline__ unsigned sptr(const void* p) {
    return (unsigned)__cvta_generic_to_shared(p);
}
__device__ __forceinline__ float tanha_(float x) {
    float y; asm("tanh.approx.f32 %0, %1;" : "=f"(y) : "f"(x)); return y;
}
__device__ __forceinline__ float sigm_(float x) {
    return fmaf(0.5f, tanha_(0.5f * x), 0.5f);
}
__device__ __forceinline__ unsigned encf_(float x) {
    unsigned u = __float_as_uint(x);
    return (u & 0x80000000u) ? ~u : (u | 0x80000000u);
}
__device__ __forceinline__ float decf_(unsigned k) {
    return __uint_as_float((k & 0x80000000u) ? (k & 0x7fffffffu) : ~k);
}
__device__ __forceinline__ void ldsm4(unsigned* r, unsigned addr) {
    asm volatile("ldmatrix.sync.aligned.m8n8.x4.shared.b16 {%0,%1,%2,%3}, [%4];"
                 : "=r"(r[0]), "=r"(r[1]), "=r"(r[2]), "=r"(r[3]) : "r"(addr));
}
__device__ __forceinline__ void mma_bf16(float* d, const unsigned* a, unsigned b0, unsigned b1) {
    asm("mma.sync.aligned.m16n8k16.row.col.f32.bf16.bf16.f32 "
        "{%0,%1,%2,%3},{%4,%5,%6,%7},{%8,%9},{%0,%1,%2,%3};"
        : "+f"(d[0]), "+f"(d[1]), "+f"(d[2]), "+f"(d[3])
        : "r"(a[0]), "r"(a[1]), "r"(a[2]), "r"(a[3]), "r"(b0), "r"(b1));
}
__device__ __forceinline__ unsigned packbf2(float lo, float hi) {
    __nv_bfloat162 p = __float22bfloat162_rn(make_float2(lo, hi));
    return *reinterpret_cast<unsigned*>(&p);
}
__device__ __forceinline__ float2 unpackbf2(unsigned u) {
    return __bfloat1622float2(*reinterpret_cast<__nv_bfloat162*>(&u));
}
__device__ __forceinline__ void cp_wait0() { asm volatile("cp.async.wait_group 0;"); }
__device__ __forceinline__ void cp_wait1() { asm volatile("cp.async.wait_group 1;"); }

// ---------------------------------------------------------------------------
// Kernel 0: weights fp32 -> bf16; reset pooling accumulators + counter
// ---------------------------------------------------------------------------
__global__ void prep_kernel(const float* __restrict__ w_ih, const float* __restrict__ w_hh) {
    int i = blockIdx.x * blockDim.x + threadIdx.x;
    if (i < GG * EE) {
        g_wih16[i] = __float2bfloat16(w_ih[i]);
        g_whh16[i] = __float2bfloat16(w_hh[i]);
    }
    if (i < BB * HH) g_featu[i] = 0u;
    if (i == 0) g_done = 0u;
}

// ---------------------------------------------------------------------------
// Stage a full 512x128 bf16 weight matrix into smem, 16B-chunk swizzled
// ---------------------------------------------------------------------------
__device__ __forceinline__ void stage_w(const __nv_bfloat16* __restrict__ src, char* w_sc, int tid) {
    const uint4* s = (const uint4*)src;
    uint4* d = (uint4*)w_sc;
    #pragma unroll
    for (int i = 0; i < 32; ++i) {
        int id  = i * 256 + tid;
        int gs  = id >> 11;
        int rem = id & 2047;
        int n   = rem >> 4;
        int c   = rem & 15;
        d[gs * 2048 + n * 16 + (c ^ (n & 7))] = s[id];
    }
}

// ---------------------------------------------------------------------------
// cp.async prefetch of one half-step's xproj rows (32 rows x 1KB)
// ---------------------------------------------------------------------------
__device__ __forceinline__ void prefetch_xh(const __nv_bfloat16* __restrict__ xbase,
                                            int w0, int half, int t, int tid, char* x_sc) {
    #pragma unroll
    for (int i = 0; i < 8; ++i) {
        int id = i * 256 + tid;
        int r  = id >> 6;                     // 0..31
        int c  = id & 63;
        int tok = min(w0 + half * 32 + r, WW - 1) + t;
        const char* src = (const char*)(xbase + (size_t)tok * GG) + c * 16;
        unsigned daddr = sptr(x_sc + (half * 32 + r) * X_STRIDE + c * 16);
        asm volatile("cp.async.cg.shared.global [%0], [%1], 16;" :: "r"(daddr), "l"(src));
    }
    asm volatile("cp.async.commit_group;");
}

// ---------------------------------------------------------------------------
// Load X(t) for one half into accumulators (smem -> regs, bf16 -> f32)
// ---------------------------------------------------------------------------
__device__ __forceinline__ void load_x(const char* x_sc, int half, int g, int tq, int nw0,
                                       float (&acc)[4][2][2][4]) {
    #pragma unroll
    for (int mt = 0; mt < 2; ++mt)
        #pragma unroll
        for (int hh = 0; hh < 2; ++hh) {
            const char* xr = x_sc + (half * 32 + mt * 16 + g + 8 * hh) * X_STRIDE;
            #pragma unroll
            for (int gs = 0; gs < 4; ++gs)
                #pragma unroll
                for (int nt = 0; nt < 2; ++nt) {
                    unsigned u = *(const unsigned*)(xr + (gs * 128 + nw0 + nt * 8 + 2 * tq) * 2);
                    float2 v = unpackbf2(u);
                    acc[gs][mt][nt][2 * hh]     = v.x;
                    acc[gs][mt][nt][2 * hh + 1] = v.y;
                }
        }
}

// ---------------------------------------------------------------------------
// One phase: GEMM of one half interleaved with the cell update of the OTHER
// half (independent rows -> tensor/MUFU pipes overlap).
// CM: 0 = no cell, 1 = cell + store h to smem, 2 = cell + pool max
// ---------------------------------------------------------------------------
template<bool DO_GEMM, int CM>
__device__ __forceinline__ void run_phase(
    unsigned aB0, unsigned aB1, unsigned bB,
    float (&accG)[4][2][2][4], float (&accC)[4][2][2][4],
    float (&cC)[2][2][4], float (&pmax)[2][2],
    char* a_store, int g, int tq, int rs, int qb, int qh, int nw0)
{
    #pragma unroll
    for (int ks = 0; ks < 8; ++ks) {
        if (DO_GEMM) {
            unsigned af0[4], af1[4];
            unsigned ca = ((unsigned)((2 * ks + qh) ^ rs)) << 4;
            ldsm4(af0, aB0 + ca);
            ldsm4(af1, aB1 + ca);
            unsigned cb = ((unsigned)((2 * ks + qb) ^ rs)) << 4;
            #pragma unroll
            for (int gs = 0; gs < 4; ++gs) {
                unsigned bf[4];
                ldsm4(bf, bB + gs * 32768 + cb);
                mma_bf16(accG[gs][0][0], af0, bf[0], bf[1]);
                mma_bf16(accG[gs][0][1], af0, bf[2], bf[3]);
                mma_bf16(accG[gs][1][0], af1, bf[0], bf[1]);
                mma_bf16(accG[gs][1][1], af1, bf[2], bf[3]);
            }
        }
        if (CM) {
            const int mt = ks >> 2, nt = (ks >> 1) & 1, hh = ks & 1;
            float h0, h1;
            {
                float gi = accC[0][mt][nt][2 * hh], gf = accC[1][mt][nt][2 * hh];
                float gg = accC[2][mt][nt][2 * hh], go = accC[3][mt][nt][2 * hh];
                float cn = sigm_(gf) * cC[mt][nt][2 * hh] + sigm_(gi) * tanha_(gg);
                cC[mt][nt][2 * hh] = cn;
                h0 = sigm_(go) * tanha_(cn);
            }
            {
                float gi = accC[0][mt][nt][2 * hh + 1], gf = accC[1][mt][nt][2 * hh + 1];
                float gg = accC[2][mt][nt][2 * hh + 1], go = accC[3][mt][nt][2 * hh + 1];
                float cn = sigm_(gf) * cC[mt][nt][2 * hh + 1] + sigm_(gi) * tanha_(gg);
                cC[mt][nt][2 * hh + 1] = cn;
                h1 = sigm_(go) * tanha_(cn);
            }
            if (CM == 1) {
                int r   = mt * 16 + g + 8 * hh;
                int cb0 = (nw0 >> 3) + nt;
                *(unsigned*)(a_store + r * 256 + ((cb0 ^ g) << 4) + 4 * tq) = packbf2(h0, h1);
            } else {
                pmax[nt][0] = fmaxf(pmax[nt][0], h0);
                pmax[nt][1] = fmaxf(pmax[nt][1], h1);
            }
        }
    }
}

// ---------------------------------------------------------------------------
// Kernel 1: xproj = emb . w_ih^T + b_ih + b_hh  (bf16 out); 4 tiles per CTA
// ---------------------------------------------------------------------------
__global__ __launch_bounds__(NTHREADS, 1)
void xproj_kernel(const int* __restrict__ inputs,
                  const float* __restrict__ embed,
                  const float* __restrict__ b_ih,
                  const float* __restrict__ b_hh)
{
    extern __shared__ char smem[];
    char* w_sc = smem;
    char* a_sc = smem + W_BYTES;

    const int tid  = threadIdx.x;
    const int lane = tid & 31;
    const int wid  = tid >> 5;
    const int g    = lane >> 2;
    const int tq   = lane & 3;
    const int rs   = lane & 7;
    const int qb   = (lane >> 3) & 1;
    const int qh   = (lane >> 4) & 1;
    const int m0w  = (wid >> 2) * 32;
    const int n0w  = (wid & 3) * 32;

    stage_w(g_wih16, w_sc, tid);

    float bias[4][4][2];
    #pragma unroll
    for (int gs = 0; gs < 4; ++gs)
        #pragma unroll
        for (int nt = 0; nt < 4; ++nt) {
            int col = gs * 128 + n0w + nt * 8 + 2 * tq;
            float2 bi = *(const float2*)&b_ih[col];
            float2 bh = *(const float2*)&b_hh[col];
            bias[gs][nt][0] = bi.x + bh.x;
            bias[gs][nt][1] = bi.y + bh.y;
        }

    unsigned aS = sptr(a_sc), wS = sptr(w_sc);
    unsigned aBase0 = aS + (m0w + rs + 8 * qb) * 256;
    unsigned aBase1 = aBase0 + 16 * 256;
    unsigned bBase0 = wS + (n0w + rs + 8 * qh) * 256;

    for (int tile = 0; tile < XP_TILES; ++tile) {
        const int t0 = (blockIdx.x * XP_TILES + tile) * MT;
        __syncthreads();
        {
            int r = tid >> 2, th = tid & 3;
            const float4* erow = (const float4*)(embed + (size_t)inputs[t0 + r] * EE) + th * 8;
            #pragma unroll
            for (int j = 0; j < 4; ++j) {
                float4 v0 = erow[2 * j], v1 = erow[2 * j + 1];
                uint4 u;
                u.x = packbf2(v0.x, v0.y); u.y = packbf2(v0.z, v0.w);
                u.z = packbf2(v1.x, v1.y); u.w = packbf2(v1.z, v1.w);
                int c = th * 4 + j;
                *(uint4*)(a_sc + r * 256 + ((c ^ (r & 7)) << 4)) = u;
            }
        }
        __syncthreads();

        float acc[4][2][4][4];
        #pragma unroll
        for (int gs = 0; gs < 4; ++gs)
            #pragma unroll
            for (int nt = 0; nt < 4; ++nt)
                #pragma unroll
                for (int mt = 0; mt < 2; ++mt) {
                    acc[gs][mt][nt][0] = bias[gs][nt][0]; acc[gs][mt][nt][1] = bias[gs][nt][1];
                    acc[gs][mt][nt][2] = bias[gs][nt][0]; acc[gs][mt][nt][3] = bias[gs][nt][1];
                }

        #pragma unroll
        for (int ks = 0; ks < 8; ++ks) {
            unsigned af0[4], af1[4];
            unsigned ca = ((unsigned)((2 * ks + qh) ^ rs)) << 4;
            ldsm4(af0, aBase0 + ca);
            ldsm4(af1, aBase1 + ca);
            unsigned cb = ((unsigned)((2 * ks + qb) ^ rs)) << 4;
            #pragma unroll
            for (int gs = 0; gs < 4; ++gs)
                #pragma unroll
                for (int ntp = 0; ntp < 2; ++ntp) {
                    unsigned bf[4];
                    ldsm4(bf, bBase0 + ntp * 4096 + (gs << 15) + cb);
                    mma_bf16(acc[gs][0][2 * ntp],     af0, bf[0], bf[1]);
                    mma_bf16(acc[gs][0][2 * ntp + 1], af0, bf[2], bf[3]);
                    mma_bf16(acc[gs][1][2 * ntp],     af1, bf[0], bf[1]);
                    mma_bf16(acc[gs][1][2 * ntp + 1], af1, bf[2], bf[3]);
                }
        }

        #pragma unroll
        for (int gs = 0; gs < 4; ++gs)
            #pragma unroll
            for (int mt = 0; mt < 2; ++mt)
                #pragma unroll
                for (int hh = 0; hh < 2; ++hh) {
                    int r = m0w + mt * 16 + g + 8 * hh;
                    __nv_bfloat16* orow = g_xproj + (size_t)(t0 + r) * GG;
                    #pragma unroll
                    for (int nt = 0; nt < 4; ++nt) {
                        unsigned u = packbf2(acc[gs][mt][nt][2 * hh], acc[gs][mt][nt][2 * hh + 1]);
                        *(unsigned*)&orow[gs * 128 + n0w + nt * 8 + 2 * tq] = u;
                    }
                }
    }
}

// ---------------------------------------------------------------------------
// Kernel 2: 6-step LSTM, two independent 32-row halves software-pipelined,
// fused atomicMax pool + last-CTA FC.
// ---------------------------------------------------------------------------
__global__ __launch_bounds__(NTHREADS, 1)
void lstm_kernel(const float* __restrict__ fc_w,
                 const float* __restrict__ fc_b,
                 float* __restrict__ out)
{
    extern __shared__ char smem[];
    char* w_sc = smem;                       // resident w_hh (bf16, swizzled)
    char* a_sc = smem + W_BYTES;             // h tiles: half0 @0, half1 @8192
    char* x_sc = smem + W_BYTES + A_BYTES;   // X rows (64 x X_STRIDE)

    const int tid  = threadIdx.x;
    const int lane = tid & 31;
    const int wid  = tid >> 5;
    const int g    = lane >> 2;
    const int tq   = lane & 3;
    const int rs   = lane & 7;
    const int qb   = (lane >> 3) & 1;
    const int qh   = (lane >> 4) & 1;
    const int nw0  = wid * 16;               // warp's 16-col slice of each gate chunk

    const int b  = blockIdx.y;
    const int w0 = blockIdx.x * MT;
    const __nv_bfloat16* xbase = g_xproj + (size_t)b * SS * GG;

    // prefetch X(0) for both halves, then stage weights (covers cp latency)
    prefetch_xh(xbase, w0, 0, 0, tid, x_sc);   // group: A0
    prefetch_xh(xbase, w0, 1, 0, tid, x_sc);   // group: B0
    stage_w(g_whh16, w_sc, tid);

    float accA[4][2][2][4], accB[4][2][2][4];
    float cA[2][2][4] = {}, cB[2][2][4] = {};
    float pmax[2][2] = {{-3.4e38f, -3.4e38f}, {-3.4e38f, -3.4e38f}};

    unsigned aS = sptr(a_sc), wS = sptr(w_sc);
    unsigned aA0 = aS + (rs + 8 * qb) * 256;          // half0 A frags
    unsigned aA1 = aA0 + 4096;
    unsigned aB0_ = aS + 8192 + (rs + 8 * qb) * 256;  // half1 A frags
    unsigned aB1_ = aB0_ + 4096;
    unsigned bB = wS + (nw0 + rs + 8 * qh) * 256;

    cp_wait1();          // A0 landed (B0 may be in flight)
    __syncthreads();     // weights + X_A(0) visible

    // ---- t = 0 peel ----
    load_x(x_sc, 0, g, tq, nw0, accA);                 // gates_A(0) = X only
    cp_wait0();
    __syncthreads();                                   // X_B(0) visible
    prefetch_xh(xbase, w0, 0, 1, tid, x_sc);           // A1
    load_x(x_sc, 1, g, tq, nw0, accB);                 // gates_B(0)
    run_phase<false, 1>(0, 0, 0, accB, accA, cA, pmax, a_sc, g, tq, rs, qb, qh, nw0);  // C_A(0), S_A(0)
    cp_wait0();
    __syncthreads();                                   // S_A(0) + X_A(1) visible

    // ---- steps 1..5 ----
    for (int t = 1; t < FWW; ++t) {
        // P1: GEMM_A(t) || cell_B(t-1) + store hB(t-1)
        prefetch_xh(xbase, w0, 1, t, tid, x_sc);       // B_t
        load_x(x_sc, 0, g, tq, nw0, accA);
        run_phase<true, 1>(aA0, aA1, bB, accA, accB, cB, pmax, a_sc + 8192,
                           g, tq, rs, qb, qh, nw0);
        cp_wait0();
        __syncthreads();                               // S_B(t-1) + X_B(t) visible

        if (t < FWW - 1) {
            // P2: GEMM_B(t) || cell_A(t) + store hA(t)
            prefetch_xh(xbase, w0, 0, t + 1, tid, x_sc);   // A_{t+1}
            load_x(x_sc, 1, g, tq, nw0, accB);
            run_phase<true, 1>(aB0_, aB1_, bB, accB, accA, cA, pmax, a_sc,
                               g, tq, rs, qb, qh, nw0);
            cp_wait0();
            __syncthreads();                           // S_A(t) + X_A(t+1) visible
        } else {
            // final: GEMM_B(5) || cell_A(5)->pool, then cell_B(5)->pool
            load_x(x_sc, 1, g, tq, nw0, accB);
            run_phase<true, 2>(aB0_, aB1_, bB, accB, accA, cA, pmax, a_sc,
                               g, tq, rs, qb, qh, nw0);
            run_phase<false, 2>(0, 0, 0, accA, accB, cB, pmax, a_sc,
                                g, tq, rs, qb, qh, nw0);
        }
    }

    // ---- pool: reduce over g (rows) via shfl, then one atomicMax per col ----
    #pragma unroll
    for (int nt = 0; nt < 2; ++nt)
        #pragma unroll
        for (int e = 0; e < 2; ++e) {
            float m = pmax[nt][e];
            m = fmaxf(m, __shfl_xor_sync(0xffffffffu, m, 4));
            m = fmaxf(m, __shfl_xor_sync(0xffffffffu, m, 8));
            m = fmaxf(m, __shfl_xor_sync(0xffffffffu, m, 16));
            pmax[nt][e] = m;
        }
    if (g == 0) {
        #pragma unroll
        for (int nt = 0; nt < 2; ++nt)
            #pragma unroll
            for (int e = 0; e < 2; ++e)
                atomicMax(&g_featu[b * HH + nw0 + nt * 8 + 2 * tq + e], encf_(pmax[nt][e]));
    }

    // ---- last CTA computes the FC ----
    __threadfence();
    __shared__ unsigned s_last;
    if (tid == 0) {
        unsigned old = atomicAdd(&g_done, 1u);
        s_last = (old == (unsigned)(NCTAS - 1)) ? 1u : 0u;
    }
    __syncthreads();
    if (s_last) {
        int pair = tid >> 1;          // 0..127
        int fb   = pair >> 1;         // batch
        int o    = pair & 1;          // output class
        int kh   = tid & 1;           // k half
        float s = 0.0f;
        #pragma unroll 8
        for (int k = kh * 64; k < kh * 64 + 64; ++k) {
            unsigned enc = atomicAdd(&g_featu[fb * HH + k], 0u);   // coherent read
            s += decf_(enc) * fc_w[o * HH + k];
        }
        s += __shfl_xor_sync(0xffffffffu, s, 1);
        if (kh == 0) out[fb * 2 + o] = s + fc_b[o];
    }
}

// ---------------------------------------------------------------------------
extern "C" void kernel_launch(void* const* d_in, const int* in_sizes, int n_in,
                              void* d_out, int out_size)
{
    const int*   inputs = (const int*)  d_in[0];
    // d_in[1] = lengths : unused by the reference
    const float* embed  = (const float*)d_in[2];
    const float* w_ih   = (const float*)d_in[3];
    const float* w_hh   = (const float*)d_in[4];
    const float* b_ih   = (const float*)d_in[5];
    const float* b_hh   = (const float*)d_in[6];
    const float* fc_w   = (const float*)d_in[7];
    const float* fc_b   = (const float*)d_in[8];
    float* out = (float*)d_out;

    cudaFuncSetAttribute(xproj_kernel, cudaFuncAttributeMaxDynamicSharedMemorySize, SMEM_XP);
    cudaFuncSetAttribute(lstm_kernel,  cudaFuncAttributeMaxDynamicSharedMemorySize, SMEM_LS);

    prep_kernel<<<(GG * EE + 255) / 256, 256>>>(w_ih, w_hh);
    xproj_kernel<<<NTOK / (MT * XP_TILES), NTHREADS, SMEM_XP>>>(inputs, embed, b_ih, b_hh);
    lstm_kernel<<<dim3(NTILES, BB), NTHREADS, SMEM_LS>>>(fc_w, fc_b, out);
}

// round 8
// speedup vs baseline: 11.4579x; 1.1518x over previous
#include <cuda_runtime.h>
#include <cuda_bf16.h>
#include <math.h>

#define BB   64
#define SS   512
#define EE   128
#define HH   128
#define GG   512          // 4*H
#define FWW  6
#define WW   507          // S - FW + 1
#define MT   64           // windows per CTA (2 halves of 32)
#define NTHREADS 256
#define NTILES 8          // 8*64 >= 507
#define NCTAS (NTILES*BB) // 512 CTAs

#define W_BYTES (GG*EE*2)        // 131072: resident bf16 weight (w_ih, then w_hh)
#define A_ROWS  80               // emb tile rows (72 used, padded)
#define A_BYTES (A_ROWS*256)     // 20480: emb tile / h tile (rows 0..63)
#define X_ROWS  72               // tokens w0..w0+71 (69 needed)
#define X_STRIDE 1040            // 512 bf16 + 16B pad
#define X_BYTES (X_ROWS*X_STRIDE)        // 74880
#define SMEM_F  (W_BYTES + A_BYTES + X_BYTES)   // 226432 <= 227KB

// Scratch (device globals: allocation is forbidden)
__device__ __align__(16) __nv_bfloat16 g_wih16[GG * EE];
__device__ __align__(16) __nv_bfloat16 g_whh16[GG * HH];
__device__ unsigned g_featu[BB * HH];   // order-encoded float, atomicMax pooling
__device__ unsigned g_done;             // CTA completion counter

// ---------------------------------------------------------------------------
__device__ __forceinline__ unsigned sptr(const void* p) {
    return (unsigned)__cvta_generic_to_shared(p);
}
__device__ __forceinline__ float tanha_(float x) {
    float y; asm("tanh.approx.f32 %0, %1;" : "=f"(y) : "f"(x)); return y;
}
__device__ __forceinline__ float sigm_(float x) {
    return fmaf(0.5f, tanha_(0.5f * x), 0.5f);
}
__device__ __forceinline__ unsigned encf_(float x) {
    unsigned u = __float_as_uint(x);
    return (u & 0x80000000u) ? ~u : (u | 0x80000000u);
}
__device__ __forceinline__ float decf_(unsigned k) {
    return __uint_as_float((k & 0x80000000u) ? (k & 0x7fffffffu) : ~k);
}
__device__ __forceinline__ void ldsm4(unsigned* r, unsigned addr) {
    asm volatile("ldmatrix.sync.aligned.m8n8.x4.shared.b16 {%0,%1,%2,%3}, [%4];"
                 : "=r"(r[0]), "=r"(r[1]), "=r"(r[2]), "=r"(r[3]) : "r"(addr));
}
__device__ __forceinline__ void mma_bf16(float* d, const unsigned* a, unsigned b0, unsigned b1) {
    asm("mma.sync.aligned.m16n8k16.row.col.f32.bf16.bf16.f32 "
        "{%0,%1,%2,%3},{%4,%5,%6,%7},{%8,%9},{%0,%1,%2,%3};"
        : "+f"(d[0]), "+f"(d[1]), "+f"(d[2]), "+f"(d[3])
        : "r"(a[0]), "r"(a[1]), "r"(a[2]), "r"(a[3]), "r"(b0), "r"(b1));
}
__device__ __forceinline__ unsigned packbf2(float lo, float hi) {
    __nv_bfloat162 p = __float22bfloat162_rn(make_float2(lo, hi));
    return *reinterpret_cast<unsigned*>(&p);
}
__device__ __forceinline__ float2 unpackbf2(unsigned u) {
    return __bfloat1622float2(*reinterpret_cast<__nv_bfloat162*>(&u));
}

// ---------------------------------------------------------------------------
// Kernel 0: weights fp32 -> bf16; reset pool accumulators + counter
// ---------------------------------------------------------------------------
__global__ void prep_kernel(const float* __restrict__ w_ih, const float* __restrict__ w_hh) {
    int i = blockIdx.x * blockDim.x + threadIdx.x;
    if (i < GG * EE) {
        g_wih16[i] = __float2bfloat16(w_ih[i]);
        g_whh16[i] = __float2bfloat16(w_hh[i]);
    }
    if (i < BB * HH) g_featu[i] = 0u;
    if (i == 0) g_done = 0u;
}

// ---------------------------------------------------------------------------
// Stage a full 512x128 bf16 weight matrix into smem, 16B-chunk swizzled
// ---------------------------------------------------------------------------
__device__ __forceinline__ void stage_w(const __nv_bfloat16* __restrict__ src, char* w_sc, int tid) {
    const uint4* s = (const uint4*)src;
    uint4* d = (uint4*)w_sc;
    #pragma unroll
    for (int i = 0; i < 32; ++i) {
        int id  = i * 256 + tid;
        int gs  = id >> 11;
        int rem = id & 2047;
        int n   = rem >> 4;
        int c   = rem & 15;
        d[gs * 2048 + n * 16 + (c ^ (n & 7))] = s[id];
    }
}

// ---------------------------------------------------------------------------
// Load X(t) for one half (rows = half*32 + local + t) into accumulators
// ---------------------------------------------------------------------------
__device__ __forceinline__ void load_x(const char* x_sc, int row0, int g, int tq, int nw0,
                                       float (&acc)[4][2][2][4]) {
    #pragma unroll
    for (int mt = 0; mt < 2; ++mt)
        #pragma unroll
        for (int hh = 0; hh < 2; ++hh) {
            const char* xr = x_sc + (row0 + mt * 16 + g + 8 * hh) * X_STRIDE;
            #pragma unroll
            for (int gs = 0; gs < 4; ++gs)
                #pragma unroll
                for (int nt = 0; nt < 2; ++nt) {
                    unsigned u = *(const unsigned*)(xr + (gs * 128 + nw0 + nt * 8 + 2 * tq) * 2);
                    float2 v = unpackbf2(u);
                    acc[gs][mt][nt][2 * hh]     = v.x;
                    acc[gs][mt][nt][2 * hh + 1] = v.y;
                }
        }
}

// ---------------------------------------------------------------------------
// One phase: 32-row GEMM (acc += A x W^T) interleaved with the cell update of
// the OTHER half. CM: 0 = none, 1 = cell + store h, 2 = cell + pool max
// ---------------------------------------------------------------------------
template<bool DO_GEMM, int CM>
__device__ __forceinline__ void run_phase(
    unsigned aB0, unsigned aB1, unsigned bB,
    float (&accG)[4][2][2][4], float (&accC)[4][2][2][4],
    float (&cC)[2][2][4], float (&pmax)[2][2],
    char* a_store, int g, int tq, int rs, int qb, int qh, int nw0,
    int wrow0, int wlim)
{
    #pragma unroll
    for (int ks = 0; ks < 8; ++ks) {
        if (DO_GEMM) {
            unsigned af0[4], af1[4];
            unsigned ca = ((unsigned)((2 * ks + qh) ^ rs)) << 4;
            ldsm4(af0, aB0 + ca);
            ldsm4(af1, aB1 + ca);
            unsigned cb = ((unsigned)((2 * ks + qb) ^ rs)) << 4;
            #pragma unroll
            for (int gs = 0; gs < 4; ++gs) {
                unsigned bf[4];
                ldsm4(bf, bB + gs * 32768 + cb);
                mma_bf16(accG[gs][0][0], af0, bf[0], bf[1]);
                mma_bf16(accG[gs][0][1], af0, bf[2], bf[3]);
                mma_bf16(accG[gs][1][0], af1, bf[0], bf[1]);
                mma_bf16(accG[gs][1][1], af1, bf[2], bf[3]);
            }
        }
        if (CM) {
            const int mt = ks >> 2, nt = (ks >> 1) & 1, hh = ks & 1;
            float h0, h1;
            {
                float gi = accC[0][mt][nt][2 * hh], gf = accC[1][mt][nt][2 * hh];
                float gg = accC[2][mt][nt][2 * hh], go = accC[3][mt][nt][2 * hh];
                float cn = sigm_(gf) * cC[mt][nt][2 * hh] + sigm_(gi) * tanha_(gg);
                cC[mt][nt][2 * hh] = cn;
                h0 = sigm_(go) * tanha_(cn);
            }
            {
                float gi = accC[0][mt][nt][2 * hh + 1], gf = accC[1][mt][nt][2 * hh + 1];
                float gg = accC[2][mt][nt][2 * hh + 1], go = accC[3][mt][nt][2 * hh + 1];
                float cn = sigm_(gf) * cC[mt][nt][2 * hh + 1] + sigm_(gi) * tanha_(gg);
                cC[mt][nt][2 * hh + 1] = cn;
                h1 = sigm_(go) * tanha_(cn);
            }
            if (CM == 1) {
                int r   = mt * 16 + g + 8 * hh;
                int cb0 = (nw0 >> 3) + nt;
                *(unsigned*)(a_store + r * 256 + ((cb0 ^ g) << 4) + 4 * tq) = packbf2(h0, h1);
            } else {
                if (wrow0 + mt * 16 + g + 8 * hh < wlim) {   // exclude invalid windows
                    pmax[nt][0] = fmaxf(pmax[nt][0], h0);
                    pmax[nt][1] = fmaxf(pmax[nt][1], h1);
                }
            }
        }
    }
}

// ---------------------------------------------------------------------------
// Fused kernel: X = emb@w_ih^T + bias (in smem), then 6-step LSTM + pool + FC
// ---------------------------------------------------------------------------
__global__ __launch_bounds__(NTHREADS, 1)
void lstm_kernel(const int* __restrict__ inputs,
                 const float* __restrict__ embed,
                 const float* __restrict__ b_ih,
                 const float* __restrict__ b_hh,
                 const float* __restrict__ fc_w,
                 const float* __restrict__ fc_b,
                 float* __restrict__ out)
{
    extern __shared__ char smem[];
    char* w_sc = smem;                       // weights (w_ih, then w_hh)
    char* a_sc = smem + W_BYTES;             // emb tile (80 rows) / h tiles (rows 0..63)
    char* x_sc = smem + W_BYTES + A_BYTES;   // X: 72 rows x X_STRIDE

    const int tid  = threadIdx.x;
    const int lane = tid & 31;
    const int wid  = tid >> 5;
    const int g    = lane >> 2;
    const int tq   = lane & 3;
    const int rs   = lane & 7;
    const int qb   = (lane >> 3) & 1;
    const int qh   = (lane >> 4) & 1;
    const int nw0  = wid * 16;               // warp's 16-col slice per gate chunk

    const int b    = blockIdx.y;
    const int w0   = blockIdx.x * MT;
    const int wlim = WW - w0;                // valid local windows

    // ---- phase 0: stage w_ih + gather embeddings ----
    stage_w(g_wih16, w_sc, tid);
    {
        // rows 0..63: 4 threads/row, 32 cols each
        int r = tid >> 2, th = tid & 3;
        int tok = min(w0 + r, SS - 1);
        const float4* erow = (const float4*)(embed + (size_t)inputs[b * SS + tok] * EE) + th * 8;
        #pragma unroll
        for (int j = 0; j < 4; ++j) {
            float4 v0 = erow[2 * j], v1 = erow[2 * j + 1];
            uint4 u;
            u.x = packbf2(v0.x, v0.y); u.y = packbf2(v0.z, v0.w);
            u.z = packbf2(v1.x, v1.y); u.w = packbf2(v1.z, v1.w);
            int c = th * 4 + j;
            *(uint4*)(a_sc + r * 256 + ((c ^ (r & 7)) << 4)) = u;
        }
        // rows 64..79: 16 threads/row, 8 cols each
        int r2 = 64 + (tid >> 4), th2 = tid & 15;
        int tok2 = min(w0 + r2, SS - 1);
        const float4* erow2 = (const float4*)(embed + (size_t)inputs[b * SS + tok2] * EE) + th2 * 2;
        float4 w0v = erow2[0], w1v = erow2[1];
        uint4 u2;
        u2.x = packbf2(w0v.x, w0v.y); u2.y = packbf2(w0v.z, w0v.w);
        u2.z = packbf2(w1v.x, w1v.y); u2.w = packbf2(w1v.z, w1v.w);
        *(uint4*)(a_sc + r2 * 256 + ((th2 ^ (r2 & 7)) << 4)) = u2;
    }

    // bias (hoisted; added into X)
    float bias[4][2][2];
    #pragma unroll
    for (int gs = 0; gs < 4; ++gs)
        #pragma unroll
        for (int nt = 0; nt < 2; ++nt) {
            int col = gs * 128 + nw0 + nt * 8 + 2 * tq;
            float2 bi = *(const float2*)&b_ih[col];
            float2 bh = *(const float2*)&b_hh[col];
            bias[gs][nt][0] = bi.x + bh.x;
            bias[gs][nt][1] = bi.y + bh.y;
        }

    unsigned aS = sptr(a_sc), wS = sptr(w_sc);
    unsigned bB = wS + (nw0 + rs + 8 * qh) * 256;

    __syncthreads();   // emb + w_ih staged

    // ---- phase 1: X = emb @ w_ih^T + bias, three 32-row passes ----
    float accA[4][2][2][4], accB[4][2][2][4];
    float cA[2][2][4] = {}, cB[2][2][4] = {};
    float pmax[2][2] = {{-3.4e38f, -3.4e38f}, {-3.4e38f, -3.4e38f}};

    #pragma unroll
    for (int p = 0; p < 3; ++p) {
        #pragma unroll
        for (int gs = 0; gs < 4; ++gs)
            #pragma unroll
            for (int nt = 0; nt < 2; ++nt)
                #pragma unroll
                for (int mt = 0; mt < 2; ++mt) {
                    accA[gs][mt][nt][0] = bias[gs][nt][0]; accA[gs][mt][nt][1] = bias[gs][nt][1];
                    accA[gs][mt][nt][2] = bias[gs][nt][0]; accA[gs][mt][nt][3] = bias[gs][nt][1];
                }
        unsigned aP0 = aS + (32 * p + rs + 8 * qb) * 256;
        unsigned aP1 = aP0 + 4096;
        run_phase<true, 0>(aP0, aP1, bB, accA, accB, cB, pmax, a_sc,
                           g, tq, rs, qb, qh, nw0, 0, 0);
        // store X rows 32p..32p+31
        #pragma unroll
        for (int gs = 0; gs < 4; ++gs)
            #pragma unroll
            for (int mt = 0; mt < 2; ++mt)
                #pragma unroll
                for (int hh = 0; hh < 2; ++hh) {
                    int r = 32 * p + mt * 16 + g + 8 * hh;
                    if (r < X_ROWS) {
                        char* xr = x_sc + r * X_STRIDE;
                        #pragma unroll
                        for (int nt = 0; nt < 2; ++nt)
                            *(unsigned*)(xr + (gs * 128 + nw0 + nt * 8 + 2 * tq) * 2) =
                                packbf2(accA[gs][mt][nt][2 * hh], accA[gs][mt][nt][2 * hh + 1]);
                    }
                }
    }

    __syncthreads();            // all w_ih reads + emb reads done
    stage_w(g_whh16, w_sc, tid);  // W := w_hh

    unsigned aA0  = aS + (rs + 8 * qb) * 256;          // half0 h frags
    unsigned aA1  = aA0 + 4096;
    unsigned aB0_ = aS + 8192 + (rs + 8 * qb) * 256;   // half1 h frags
    unsigned aB1_ = aB0_ + 4096;

    __syncthreads();            // w_hh + X visible

    // ---- t = 0 peel: gates = X only (h = 0) ----
    load_x(x_sc, 0, g, tq, nw0, accA);
    load_x(x_sc, 32, g, tq, nw0, accB);
    run_phase<false, 1>(0, 0, 0, accB, accA, cA, pmax, a_sc,
                        g, tq, rs, qb, qh, nw0, 0, wlim);   // cell_A(0) -> store hA
    __syncthreads();

    // ---- steps 1..5 ----
    for (int t = 1; t < FWW; ++t) {
        // P1: GEMM_A(t) || cell_B(t-1) + store hB
        load_x(x_sc, 0 + t, g, tq, nw0, accA);
        run_phase<true, 1>(aA0, aA1, bB, accA, accB, cB, pmax, a_sc + 8192,
                           g, tq, rs, qb, qh, nw0, 32, wlim);
        __syncthreads();

        if (t < FWW - 1) {
            // P2: GEMM_B(t) || cell_A(t) + store hA
            load_x(x_sc, 32 + t, g, tq, nw0, accB);
            run_phase<true, 1>(aB0_, aB1_, bB, accB, accA, cA, pmax, a_sc,
                               g, tq, rs, qb, qh, nw0, 0, wlim);
            __syncthreads();
        } else {
            // final: GEMM_B(5) || cell_A(5)->pool, then cell_B(5)->pool
            load_x(x_sc, 32 + t, g, tq, nw0, accB);
            run_phase<true, 2>(aB0_, aB1_, bB, accB, accA, cA, pmax, a_sc,
                               g, tq, rs, qb, qh, nw0, 0, wlim);
            run_phase<false, 2>(0, 0, 0, accA, accB, cB, pmax, a_sc,
                                g, tq, rs, qb, qh, nw0, 32, wlim);
        }
    }

    // ---- pool: reduce over rows (g) via shfl, one atomicMax per column ----
    #pragma unroll
    for (int nt = 0; nt < 2; ++nt)
        #pragma unroll
        for (int e = 0; e < 2; ++e) {
            float m = pmax[nt][e];
            m = fmaxf(m, __shfl_xor_sync(0xffffffffu, m, 4));
            m = fmaxf(m, __shfl_xor_sync(0xffffffffu, m, 8));
            m = fmaxf(m, __shfl_xor_sync(0xffffffffu, m, 16));
            pmax[nt][e] = m;
        }
    if (g == 0) {
        #pragma unroll
        for (int nt = 0; nt < 2; ++nt)
            #pragma unroll
            for (int e = 0; e < 2; ++e)
                atomicMax(&g_featu[b * HH + nw0 + nt * 8 + 2 * tq + e], encf_(pmax[nt][e]));
    }

    // ---- last CTA computes the FC ----
    __threadfence();
    __shared__ unsigned s_last;
    if (tid == 0) {
        unsigned old = atomicAdd(&g_done, 1u);
        s_last = (old == (unsigned)(NCTAS - 1)) ? 1u : 0u;
    }
    __syncthreads();
    if (s_last) {
        int pair = tid >> 1;          // 0..127
        int fb   = pair >> 1;         // batch
        int o    = pair & 1;          // output class
        int kh   = tid & 1;           // k half
        float s = 0.0f;
        #pragma unroll 8
        for (int k = kh * 64; k < kh * 64 + 64; ++k) {
            unsigned enc = atomicAdd(&g_featu[fb * HH + k], 0u);   // coherent read
            s += decf_(enc) * fc_w[o * HH + k];
        }
        s += __shfl_xor_sync(0xffffffffu, s, 1);
        if (kh == 0) out[fb * 2 + o] = s + fc_b[o];
    }
}

// ---------------------------------------------------------------------------
extern "C" void kernel_launch(void* const* d_in, const int* in_sizes, int n_in,
                              void* d_out, int out_size)
{
    const int*   inputs = (const int*)  d_in[0];
    // d_in[1] = lengths : unused by the reference
    const float* embed  = (const float*)d_in[2];
    const float* w_ih   = (const float*)d_in[3];
    const float* w_hh   = (const float*)d_in[4];
    const float* b_ih   = (const float*)d_in[5];
    const float* b_hh   = (const float*)d_in[6];
    const float* fc_w   = (const float*)d_in[7];
    const float* fc_b   = (const float*)d_in[8];
    float* out = (float*)d_out;

    cudaFuncSetAttribute(lstm_kernel, cudaFuncAttributeMaxDynamicSharedMemorySize, SMEM_F);

    prep_kernel<<<(GG * EE + 255) / 256, 256>>>(w_ih, w_hh);
    lstm_kernel<<<dim3(NTILES, BB), NTHREADS, SMEM_F>>>(inputs, embed, b_ih, b_hh,
                                                        fc_w, fc_b, out);
}